// round 1
// baseline (speedup 1.0000x reference)
#include <cuda_runtime.h>
#include <math.h>

#define Bb 2
#define SFULL 8192
#define Dd 1536
#define Ss 512
#define Hh 32
#define Cc 128
#define HC 4096
#define Ff 32
#define PAIRF 128
#define P2 1024

// ---------------- scratch (device globals; no allocations allowed) ----------------
__device__ float g_xp[Bb*Ss*Dd];          // pooled + rmsnorm
__device__ float g_g [Bb*Ss*Dd];          // gelu(xp)
__device__ float g_q [Bb*Ss*HC];          // xp @ w_q   [b*512+s][h*128+c]
__device__ float g_k [Bb*Ss*HC];          // xp @ w_k
__device__ float g_pos[P2*HC];            // pos_encoding [p][h*128+c]
__device__ float g_sufq[Ff*HC];           // suffix sums of w_pos rows 0..31
__device__ float g_sufs[Ff*HC];           // suffix sums of w_pos rows 32..63
__device__ float g_cw[Ff];                // center widths
__device__ float g_yq[Bb*Ss*PAIRF];
__device__ float g_yk[Bb*Ss*PAIRF];
__device__ float g_ypart[16*Bb*Ss*PAIRF]; // k-split partials (8 for yq, 8 for yk)
__device__ float g_rq[(size_t)Bb*Hh*Ss*P2];   // rel_q logits [bh][q][p]
__device__ float g_rk[(size_t)Bb*Hh*Ss*P2];   // rel_k logits [bh][k][p]
__device__ float g_a [(size_t)Bb*Hh*Ss*Ss];   // a [bh][q][k]

// ---------------- small init kernels ----------------
__global__ void init_cw_kernel() {
    int f = threadIdx.x;
    if (f < Ff)
        g_cw[f] = (float)((double)f + exp(log(481.0) * ((double)f / 32.0)));
}

// pool(16) + RMSNorm + gelu. one block per pooled row.
__global__ void __launch_bounds__(384) pool_norm_kernel(const float* __restrict__ x,
                                                        const float* __restrict__ scale) {
    int row = blockIdx.x;                 // b*512 + sp ; x offset = row*16*Dd (b*8192 = b*512*16)
    int t = threadIdx.x;
    const float* xr = x + (size_t)row * 16 * Dd;
    float pooled[4];
    float ss = 0.f;
#pragma unroll
    for (int u = 0; u < 4; ++u) {
        int d = t + u * 384;
        float s = 0.f;
#pragma unroll
        for (int j = 0; j < 16; ++j) s += xr[(size_t)j * Dd + d];
        s *= 0.0625f;
        pooled[u] = s;
        ss += s * s;
    }
    __shared__ float red[13];
#pragma unroll
    for (int o = 16; o; o >>= 1) ss += __shfl_xor_sync(0xffffffffu, ss, o);
    if ((t & 31) == 0) red[t >> 5] = ss;
    __syncthreads();
    if (t == 0) {
        float tot = 0.f;
        for (int i = 0; i < 12; ++i) tot += red[i];
        red[12] = rsqrtf(tot * (1.f / 1536.f) + 1e-5f);
    }
    __syncthreads();
    float inv = red[12];
#pragma unroll
    for (int u = 0; u < 4; ++u) {
        int d = t + u * 384;
        float v = pooled[u] * inv * scale[d];
        g_xp[(size_t)row * Dd + d] = v;
        float v3 = v * v * v;
        float gl = 0.5f * v * (1.f + tanhf(0.7978845608028654f * (v + 0.044715f * v3)));
        g_g[(size_t)row * Dd + d] = gl;
    }
}

// suffix sums of w_pos: pos_encoding(p) = b_pos + sufq[fmin] + sign*sufs[fmin]
__global__ void suffix_kernel(const float* __restrict__ wpos) {
    int hc = blockIdx.x * 256 + threadIdx.x;
    float aq = 0.f, as = 0.f;
    for (int f = Ff - 1; f >= 0; --f) {
        aq += wpos[f * HC + hc];
        as += wpos[(Ff + f) * HC + hc];
        g_sufq[f * HC + hc] = aq;
        g_sufs[f * HC + hc] = as;
    }
}

__global__ void posenc_kernel(const float* __restrict__ bpos) {
    int p = blockIdx.x;
    int hc = blockIdx.y * 512 + threadIdx.x;
    int dist = (p >= 512) ? p - 512 : 512 - p;
    int fmin = Ff;
#pragma unroll
    for (int f = Ff - 1; f >= 0; --f)
        if (g_cw[f] > (float)dist) fmin = f;
    float v = bpos[hc];
    if (fmin < Ff) {
        float sg = (p > 512) ? 1.f : ((p < 512) ? -1.f : 0.f);
        v += g_sufq[fmin * HC + hc] + sg * g_sufs[fmin * HC + hc];
    }
    g_pos[(size_t)p * HC + hc] = v;
}

// ---------------- fp32 GEMM micro-kernel (128x128 tile, 8x8 per thread) ----------------
template <int LA, int LB>
__device__ __forceinline__ void mm16(const float* As, const float* Bs, float (*acc)[8],
                                     int tx, int ty) {
#pragma unroll
    for (int kk = 0; kk < 16; ++kk) {
        float4 a0 = *(const float4*)(As + kk * LA + 8 * ty);
        float4 a1 = *(const float4*)(As + kk * LA + 8 * ty + 4);
        float4 b0 = *(const float4*)(Bs + kk * LB + 8 * tx);
        float4 b1 = *(const float4*)(Bs + kk * LB + 8 * tx + 4);
        float av[8] = {a0.x, a0.y, a0.z, a0.w, a1.x, a1.y, a1.z, a1.w};
        float bv[8] = {b0.x, b0.y, b0.z, b0.w, b1.x, b1.y, b1.z, b1.w};
#pragma unroll
        for (int i = 0; i < 8; ++i)
#pragma unroll
            for (int j = 0; j < 8; ++j) acc[i][j] = fmaf(av[i], bv[j], acc[i][j]);
    }
}

// NN: C[M,N] = A[M,K] @ B[K,N] over k range [z*ksz, (z+1)*ksz), C += z*coffs
__global__ void __launch_bounds__(256) sgemm_nn(const float* __restrict__ A,
                                                const float* __restrict__ Bm,
                                                float* __restrict__ C,
                                                int lda, int ldb, int ldc,
                                                int ksz, long long coffs) {
    __shared__ float As[16][132];
    __shared__ float Bs[16][128];
    int m0 = blockIdx.y * 128, n0 = blockIdx.x * 128;
    C += (size_t)blockIdx.z * (size_t)coffs;
    int kstart = blockIdx.z * ksz;
    int t = threadIdx.x, tx = t & 15, ty = t >> 4;
    int aRow = t >> 2, aCol4 = (t & 3) * 4;
    int bRow = t >> 5, bCol4 = (t & 31) * 4;
    float acc[8][8] = {};
    for (int kb = kstart; kb < kstart + ksz; kb += 16) {
#pragma unroll
        for (int r = 0; r < 2; ++r) {
            float4 v = *(const float4*)&A[(size_t)(m0 + aRow + 64 * r) * lda + kb + aCol4];
            As[aCol4 + 0][aRow + 64 * r] = v.x;
            As[aCol4 + 1][aRow + 64 * r] = v.y;
            As[aCol4 + 2][aRow + 64 * r] = v.z;
            As[aCol4 + 3][aRow + 64 * r] = v.w;
        }
#pragma unroll
        for (int r = 0; r < 2; ++r)
            *(float4*)&Bs[bRow + 8 * r][bCol4] =
                *(const float4*)&Bm[(size_t)(kb + bRow + 8 * r) * ldb + n0 + bCol4];
        __syncthreads();
        mm16<132, 128>(&As[0][0], &Bs[0][0], acc, tx, ty);
        __syncthreads();
    }
#pragma unroll
    for (int i = 0; i < 8; ++i) {
        size_t off = (size_t)(m0 + 8 * ty + i) * ldc + n0 + 8 * tx;
        *(float4*)&C[off]     = make_float4(acc[i][0], acc[i][1], acc[i][2], acc[i][3]);
        *(float4*)&C[off + 4] = make_float4(acc[i][4], acc[i][5], acc[i][6], acc[i][7]);
    }
}

__global__ void reduce_y_kernel() {
    int i = blockIdx.x * 256 + threadIdx.x;   // 131072 total
    float sq = 0.f, sk = 0.f;
#pragma unroll
    for (int s = 0; s < 8; ++s) {
        sq += g_ypart[s * 131072 + i];
        sk += g_ypart[(8 + s) * 131072 + i];
    }
    g_yq[i] = sq;
    g_yk[i] = sk;
}

// NT: rel logits. per z: side(q/k), bh. C[512,1024] = (Q_h + bias) @ pos_h^T
__global__ void __launch_bounds__(256) rel_gemm(const float* __restrict__ qrb,
                                                const float* __restrict__ krb) {
    __shared__ float As[16][132];
    __shared__ float Bs[16][132];
    int z = blockIdx.z;
    int side = z >> 6, bh = z & 63, b = bh >> 5, h = bh & 31;
    const float* A = (side ? g_k : g_q) + (size_t)b * Ss * HC + h * Cc;
    const float* rb = (side ? krb : qrb) + h * Cc;
    const float* Bp = g_pos + h * Cc;
    float* Cp = (side ? g_rk : g_rq) + (size_t)bh * (Ss * P2);
    int m0 = blockIdx.y * 128, n0 = blockIdx.x * 128;
    int t = threadIdx.x, tx = t & 15, ty = t >> 4;
    int aRow = t >> 2, aCol4 = (t & 3) * 4;
    float acc[8][8] = {};
    for (int kb = 0; kb < Cc; kb += 16) {
        float4 rbv = *(const float4*)&rb[kb + aCol4];
#pragma unroll
        for (int r = 0; r < 2; ++r) {
            float4 v = *(const float4*)&A[(size_t)(m0 + aRow + 64 * r) * HC + kb + aCol4];
            As[aCol4 + 0][aRow + 64 * r] = v.x + rbv.x;
            As[aCol4 + 1][aRow + 64 * r] = v.y + rbv.y;
            As[aCol4 + 2][aRow + 64 * r] = v.z + rbv.z;
            As[aCol4 + 3][aRow + 64 * r] = v.w + rbv.w;
        }
#pragma unroll
        for (int r = 0; r < 2; ++r) {
            float4 v = *(const float4*)&Bp[(size_t)(n0 + aRow + 64 * r) * HC + kb + aCol4];
            Bs[aCol4 + 0][aRow + 64 * r] = v.x;
            Bs[aCol4 + 1][aRow + 64 * r] = v.y;
            Bs[aCol4 + 2][aRow + 64 * r] = v.z;
            Bs[aCol4 + 3][aRow + 64 * r] = v.w;
        }
        __syncthreads();
        mm16<132, 132>(&As[0][0], &Bs[0][0], acc, tx, ty);
        __syncthreads();
    }
#pragma unroll
    for (int i = 0; i < 8; ++i) {
        size_t off = (size_t)(m0 + 8 * ty + i) * P2 + n0 + 8 * tx;
        *(float4*)&Cp[off]     = make_float4(acc[i][0], acc[i][1], acc[i][2], acc[i][3]);
        *(float4*)&Cp[off + 4] = make_float4(acc[i][4], acc[i][5], acc[i][6], acc[i][7]);
    }
}

// NT: a[bh][q][k] = Q_h @ K_h^T + 0.5*(rq[q, k-q+512] + rk[k, q-k+512])
__global__ void __launch_bounds__(256) a_gemm() {
    extern __shared__ float sm[];
    float* As = sm;                 // [16][132]
    float* Bs = sm + 16 * 132;      // [16][132]
    float* Rk = sm + 2 * 16 * 132;  // [128][129]
    int bh = blockIdx.z, b = bh >> 5, h = bh & 31;
    const float* A  = g_q + (size_t)b * Ss * HC + h * Cc;
    const float* Bp = g_k + (size_t)b * Ss * HC + h * Cc;
    const float* rqb = g_rq + (size_t)bh * (Ss * P2);
    const float* rkb = g_rk + (size_t)bh * (Ss * P2);
    float* Cp = g_a + (size_t)bh * (Ss * Ss);
    int m0 = blockIdx.y * 128, n0 = blockIdx.x * 128;
    int t = threadIdx.x, tx = t & 15, ty = t >> 4;
    int aRow = t >> 2, aCol4 = (t & 3) * 4;
    float acc[8][8] = {};
    for (int kb = 0; kb < Cc; kb += 16) {
#pragma unroll
        for (int r = 0; r < 2; ++r) {
            float4 v = *(const float4*)&A[(size_t)(m0 + aRow + 64 * r) * HC + kb + aCol4];
            As[(aCol4 + 0) * 132 + aRow + 64 * r] = v.x;
            As[(aCol4 + 1) * 132 + aRow + 64 * r] = v.y;
            As[(aCol4 + 2) * 132 + aRow + 64 * r] = v.z;
            As[(aCol4 + 3) * 132 + aRow + 64 * r] = v.w;
        }
#pragma unroll
        for (int r = 0; r < 2; ++r) {
            float4 v = *(const float4*)&Bp[(size_t)(n0 + aRow + 64 * r) * HC + kb + aCol4];
            Bs[(aCol4 + 0) * 132 + aRow + 64 * r] = v.x;
            Bs[(aCol4 + 1) * 132 + aRow + 64 * r] = v.y;
            Bs[(aCol4 + 2) * 132 + aRow + 64 * r] = v.z;
            Bs[(aCol4 + 3) * 132 + aRow + 64 * r] = v.w;
        }
        __syncthreads();
        mm16<132, 132>(As, Bs, acc, tx, ty);
        __syncthreads();
    }
    // stage rk band: Rk[k_local][q_local] = rk[k0+kl, (m0+ql) - k + 512]  (coalesced rows)
    for (int idx = t; idx < 128 * 128; idx += 256) {
        int kk = idx >> 7, ql = idx & 127;
        int kg = n0 + kk;
        Rk[kk * 129 + ql] = rkb[(size_t)kg * P2 + (m0 - kg + 512) + ql];
    }
    __syncthreads();
#pragma unroll
    for (int i = 0; i < 8; ++i) {
        int q = m0 + 8 * ty + i;
        float vals[8];
#pragma unroll
        for (int j = 0; j < 8; ++j) {
            int k = n0 + 8 * tx + j;
            float rq = rqb[(size_t)q * P2 + (k - q + 512)];
            vals[j] = acc[i][j] + 0.5f * (rq + Rk[(8 * tx + j) * 129 + (8 * ty + i)]);
        }
        size_t off = (size_t)q * Ss + n0 + 8 * tx;
        *(float4*)&Cp[off]     = make_float4(vals[0], vals[1], vals[2], vals[3]);
        *(float4*)&Cp[off + 4] = make_float4(vals[4], vals[5], vals[6], vals[7]);
    }
}

// final: out[b,q,k,f] = sum_h a[bh][q][k]*w_pair[h,f] + b_pair[f] + yq[b,q,f] + yk[b,k,f]
__global__ void __launch_bounds__(128) final_kernel(const float* __restrict__ wpair,
                                                    const float* __restrict__ bpair,
                                                    float* __restrict__ out) {
    int b = blockIdx.z, q = blockIdx.y, k0 = blockIdx.x * 128;
    int f = threadIdx.x;
    float wp[32];
#pragma unroll
    for (int h = 0; h < 32; ++h) wp[h] = wpair[h * 128 + f];
    float base = bpair[f] + g_yq[(size_t)(b * 512 + q) * 128 + f];
    __shared__ float as_[32][128];
    const float* abase = g_a + (size_t)b * 32 * Ss * Ss;
    for (int idx = f; idx < 32 * 128; idx += 128) {
        int h = idx >> 7, kl = idx & 127;
        as_[h][kl] = abase[((size_t)h * Ss + q) * Ss + k0 + kl];
    }
    __syncthreads();
    float* orow = out + (((size_t)(b * 512 + q)) * Ss + k0) * 128 + f;
    const float* ykrow = g_yk + (size_t)(b * 512 + k0) * 128 + f;
    for (int kl = 0; kl < 128; ++kl) {
        float acc = base + ykrow[(size_t)kl * 128];
#pragma unroll
        for (int h = 0; h < 32; ++h) acc = fmaf(as_[h][kl], wp[h], acc);
        orow[(size_t)kl * 128] = acc;
    }
}

// ---------------- launcher ----------------
extern "C" void kernel_launch(void* const* d_in, const int* in_sizes, int n_in,
                              void* d_out, int out_size) {
    const float* x        = (const float*)d_in[0];
    const float* scale    = (const float*)d_in[1];
    const float* w_q      = (const float*)d_in[2];
    const float* w_k      = (const float*)d_in[3];
    const float* w_pos    = (const float*)d_in[4];
    const float* b_pos    = (const float*)d_in[5];
    const float* q_r_bias = (const float*)d_in[6];
    const float* k_r_bias = (const float*)d_in[7];
    const float* w_yq     = (const float*)d_in[8];
    const float* w_yk     = (const float*)d_in[9];
    const float* w_pair   = (const float*)d_in[10];
    const float* b_pair   = (const float*)d_in[11];
    float* out = (float*)d_out;

    float *p_xp, *p_g, *p_q, *p_k, *p_ypart;
    cudaGetSymbolAddress((void**)&p_xp, g_xp);
    cudaGetSymbolAddress((void**)&p_g, g_g);
    cudaGetSymbolAddress((void**)&p_q, g_q);
    cudaGetSymbolAddress((void**)&p_k, g_k);
    cudaGetSymbolAddress((void**)&p_ypart, g_ypart);

    const int ASMEM = (2 * 16 * 132 + 128 * 129) * (int)sizeof(float);  // 82944 B
    cudaFuncSetAttribute(a_gemm, cudaFuncAttributeMaxDynamicSharedMemorySize, ASMEM);

    init_cw_kernel<<<1, 32>>>();
    pool_norm_kernel<<<1024, 384>>>(x, scale);
    suffix_kernel<<<16, 256>>>(w_pos);
    posenc_kernel<<<dim3(1024, 8), 512>>>(b_pos);
    // q, k projections: M=1024, N=4096, K=1536
    sgemm_nn<<<dim3(32, 8, 1), 256>>>(p_xp, w_q, p_q, Dd, HC, HC, Dd, 0);
    sgemm_nn<<<dim3(32, 8, 1), 256>>>(p_xp, w_k, p_k, Dd, HC, HC, Dd, 0);
    // y projections via k-split (8 slices of 192)
    sgemm_nn<<<dim3(1, 8, 8), 256>>>(p_g, w_yq, p_ypart, Dd, PAIRF, PAIRF, 192, 131072LL);
    sgemm_nn<<<dim3(1, 8, 8), 256>>>(p_g, w_yk, p_ypart + 8 * 131072, Dd, PAIRF, PAIRF, 192, 131072LL);
    reduce_y_kernel<<<512, 256>>>();
    // rel logits: 128 gemms of 512x1024x128
    rel_gemm<<<dim3(8, 4, 128), 256>>>(q_r_bias, k_r_bias);
    // a = QK^T + 0.5*(rq+rk) gathered: 64 gemms of 512x512x128
    a_gemm<<<dim3(4, 4, 64), 256, ASMEM>>>();
    // head->pair projection + biases + y terms
    final_kernel<<<dim3(4, 512, 2), 128>>>(w_pair, b_pair, out);
}

// round 2
// speedup vs baseline: 2.5361x; 2.5361x over previous
#include <cuda_runtime.h>
#include <math.h>
#include <stdint.h>

#define Bb 2
#define SFULL 8192
#define Dd 1536
#define Ss 512
#define Hh 32
#define Cc 128
#define HC 4096
#define Ff 32
#define PAIRF 128
#define P2 1024

// ---------------- scratch (device globals; no allocations allowed) ----------------
__device__ float g_xp[Bb*Ss*Dd];          // pooled + rmsnorm
__device__ float g_g [Bb*Ss*Dd];          // gelu(xp)
__device__ float g_q [Bb*Ss*HC];          // xp @ w_q   [b*512+s][h*128+c]
__device__ float g_k [Bb*Ss*HC];          // xp @ w_k
__device__ float g_pos[P2*HC];            // pos_encoding [p][h*128+c]
__device__ float g_sufq[Ff*HC];
__device__ float g_sufs[Ff*HC];
__device__ float g_cw[Ff];
__device__ float g_yq[Bb*Ss*PAIRF];
__device__ float g_yk[Bb*Ss*PAIRF];
__device__ float g_ypart[16*Bb*Ss*PAIRF];
__device__ float g_rq[(size_t)Bb*Hh*Ss*P2];   // rel_q logits [bh][q][p]
__device__ float g_rk[(size_t)Bb*Hh*Ss*P2];   // rel_k logits [bh][k][p]
__device__ float g_a [(size_t)Bb*Hh*Ss*Ss];   // a [bh][q][k]

// ---------------- tf32 helpers ----------------
__device__ __forceinline__ uint32_t f2tf(float f) {
    uint32_t u;
    asm("cvt.rna.tf32.f32 %0, %1;" : "=r"(u) : "f"(f));
    return u;
}

#define MMA_TF32(d, a, b) asm volatile( \
    "mma.sync.aligned.m16n8k8.row.col.f32.tf32.tf32.f32 " \
    "{%0,%1,%2,%3}, {%4,%5,%6,%7}, {%8,%9}, {%0,%1,%2,%3};\n" \
    : "+f"((d)[0]), "+f"((d)[1]), "+f"((d)[2]), "+f"((d)[3]) \
    : "r"((a)[0]), "r"((a)[1]), "r"((a)[2]), "r"((a)[3]), \
      "r"((b)[0]), "r"((b)[1]))

// ---------------- small init kernels ----------------
__global__ void init_cw_kernel() {
    int f = threadIdx.x;
    if (f < Ff)
        g_cw[f] = (float)((double)f + exp(log(481.0) * ((double)f / 32.0)));
}

// pool(16) + RMSNorm + gelu. one block per pooled row.
__global__ void __launch_bounds__(384) pool_norm_kernel(const float* __restrict__ x,
                                                        const float* __restrict__ scale) {
    int row = blockIdx.x;
    int t = threadIdx.x;
    const float* xr = x + (size_t)row * 16 * Dd;
    float pooled[4];
    float ss = 0.f;
#pragma unroll
    for (int u = 0; u < 4; ++u) {
        int d = t + u * 384;
        float s = 0.f;
#pragma unroll
        for (int j = 0; j < 16; ++j) s += xr[(size_t)j * Dd + d];
        s *= 0.0625f;
        pooled[u] = s;
        ss += s * s;
    }
    __shared__ float red[13];
#pragma unroll
    for (int o = 16; o; o >>= 1) ss += __shfl_xor_sync(0xffffffffu, ss, o);
    if ((t & 31) == 0) red[t >> 5] = ss;
    __syncthreads();
    if (t == 0) {
        float tot = 0.f;
        for (int i = 0; i < 12; ++i) tot += red[i];
        red[12] = rsqrtf(tot * (1.f / 1536.f) + 1e-5f);
    }
    __syncthreads();
    float inv = red[12];
#pragma unroll
    for (int u = 0; u < 4; ++u) {
        int d = t + u * 384;
        float v = pooled[u] * inv * scale[d];
        g_xp[(size_t)row * Dd + d] = v;
        float v3 = v * v * v;
        float gl = 0.5f * v * (1.f + tanhf(0.7978845608028654f * (v + 0.044715f * v3)));
        g_g[(size_t)row * Dd + d] = gl;
    }
}

__global__ void suffix_kernel(const float* __restrict__ wpos) {
    int hc = blockIdx.x * 256 + threadIdx.x;
    float aq = 0.f, as = 0.f;
    for (int f = Ff - 1; f >= 0; --f) {
        aq += wpos[f * HC + hc];
        as += wpos[(Ff + f) * HC + hc];
        g_sufq[f * HC + hc] = aq;
        g_sufs[f * HC + hc] = as;
    }
}

__global__ void posenc_kernel(const float* __restrict__ bpos) {
    int p = blockIdx.x;
    int hc = blockIdx.y * 512 + threadIdx.x;
    int dist = (p >= 512) ? p - 512 : 512 - p;
    int fmin = Ff;
#pragma unroll
    for (int f = Ff - 1; f >= 0; --f)
        if (g_cw[f] > (float)dist) fmin = f;
    float v = bpos[hc];
    if (fmin < Ff) {
        float sg = (p > 512) ? 1.f : ((p < 512) ? -1.f : 0.f);
        v += g_sufq[fmin * HC + hc] + sg * g_sufs[fmin * HC + hc];
    }
    g_pos[(size_t)p * HC + hc] = v;
}

__global__ void reduce_y_kernel() {
    int i = blockIdx.x * 256 + threadIdx.x;
    float sq = 0.f, sk = 0.f;
#pragma unroll
    for (int s = 0; s < 8; ++s) {
        sq += g_ypart[s * 131072 + i];
        sk += g_ypart[(8 + s) * 131072 + i];
    }
    g_yq[i] = sq;
    g_yk[i] = sk;
}

// ---------------- tf32 tensor-core GEMM (NN): C[M,N] = A[M,K] @ B[K,N] ----------------
// block 128x128, 8 warps (2x4), warp tile 64x32, K-step 32
__global__ void __launch_bounds__(256, 2) gemm_nn_tc(const float* __restrict__ A,
                                                     const float* __restrict__ Bm,
                                                     float* __restrict__ C,
                                                     int lda, int ldb, int ldc,
                                                     int ksz, long long coffs) {
    __shared__ uint32_t As[128][36];
    __shared__ uint32_t Bs[32][136];
    int m0 = blockIdx.y * 128, n0 = blockIdx.x * 128;
    C += (size_t)blockIdx.z * (size_t)coffs;
    int kstart = blockIdx.z * ksz;
    int t = threadIdx.x, lane = t & 31, wid = t >> 5;
    int grp = lane >> 2, tig = lane & 3;
    int moff = (wid >> 2) * 64, noff = (wid & 3) * 32;
    float acc[4][4][4] = {};
    for (int kb = kstart; kb < kstart + ksz; kb += 32) {
#pragma unroll
        for (int i = 0; i < 4; ++i) {
            int idx = t + 256 * i;
            int r = idx >> 3, c4 = (idx & 7) * 4;
            float4 v = *(const float4*)&A[(size_t)(m0 + r) * lda + kb + c4];
            As[r][c4] = f2tf(v.x); As[r][c4 + 1] = f2tf(v.y);
            As[r][c4 + 2] = f2tf(v.z); As[r][c4 + 3] = f2tf(v.w);
        }
#pragma unroll
        for (int i = 0; i < 4; ++i) {
            int idx = t + 256 * i;
            int r = idx >> 5, c4 = (idx & 31) * 4;
            float4 v = *(const float4*)&Bm[(size_t)(kb + r) * ldb + n0 + c4];
            Bs[r][c4] = f2tf(v.x); Bs[r][c4 + 1] = f2tf(v.y);
            Bs[r][c4 + 2] = f2tf(v.z); Bs[r][c4 + 3] = f2tf(v.w);
        }
        __syncthreads();
#pragma unroll
        for (int ks = 0; ks < 4; ++ks) {
            int kk = ks * 8;
            uint32_t af[4][4], bf[4][2];
#pragma unroll
            for (int mi = 0; mi < 4; ++mi) {
                int r = moff + 16 * mi + grp;
                af[mi][0] = As[r][kk + tig];     af[mi][1] = As[r + 8][kk + tig];
                af[mi][2] = As[r][kk + tig + 4]; af[mi][3] = As[r + 8][kk + tig + 4];
            }
#pragma unroll
            for (int ni = 0; ni < 4; ++ni) {
                int c = noff + 8 * ni + grp;
                bf[ni][0] = Bs[kk + tig][c]; bf[ni][1] = Bs[kk + tig + 4][c];
            }
#pragma unroll
            for (int mi = 0; mi < 4; ++mi)
#pragma unroll
                for (int ni = 0; ni < 4; ++ni) MMA_TF32(acc[mi][ni], af[mi], bf[ni]);
        }
        __syncthreads();
    }
#pragma unroll
    for (int mi = 0; mi < 4; ++mi) {
        int r = m0 + moff + 16 * mi + grp;
#pragma unroll
        for (int ni = 0; ni < 4; ++ni) {
            int c = n0 + noff + 8 * ni + 2 * tig;
            *(float2*)&C[(size_t)r * ldc + c] = make_float2(acc[mi][ni][0], acc[mi][ni][1]);
            *(float2*)&C[(size_t)(r + 8) * ldc + c] = make_float2(acc[mi][ni][2], acc[mi][ni][3]);
        }
    }
}

// ---------------- rel logits (NT, tf32): C[512,1024] = (Q_h + bias) @ pos_h^T ----------------
__global__ void __launch_bounds__(256, 2) rel_tc(const float* __restrict__ qrb,
                                                 const float* __restrict__ krb) {
    __shared__ uint32_t As[128][36];
    __shared__ uint32_t Bs[128][36];
    int z = blockIdx.z;
    int side = z >> 6, bh = z & 63, b = bh >> 5, h = bh & 31;
    const float* A = (side ? g_k : g_q) + (size_t)b * Ss * HC + h * Cc;
    const float* rb = (side ? krb : qrb) + h * Cc;
    const float* Bp = g_pos + h * Cc;
    float* Cp = (side ? g_rk : g_rq) + (size_t)bh * (Ss * P2);
    int m0 = blockIdx.y * 128, n0 = blockIdx.x * 128;
    int t = threadIdx.x, lane = t & 31, wid = t >> 5;
    int grp = lane >> 2, tig = lane & 3;
    int moff = (wid >> 2) * 64, noff = (wid & 3) * 32;
    float acc[4][4][4] = {};
    for (int kb = 0; kb < Cc; kb += 32) {
#pragma unroll
        for (int i = 0; i < 4; ++i) {
            int idx = t + 256 * i;
            int r = idx >> 3, c4 = (idx & 7) * 4;
            float4 rv = *(const float4*)&rb[kb + c4];
            float4 v = *(const float4*)&A[(size_t)(m0 + r) * HC + kb + c4];
            As[r][c4] = f2tf(v.x + rv.x); As[r][c4 + 1] = f2tf(v.y + rv.y);
            As[r][c4 + 2] = f2tf(v.z + rv.z); As[r][c4 + 3] = f2tf(v.w + rv.w);
        }
#pragma unroll
        for (int i = 0; i < 4; ++i) {
            int idx = t + 256 * i;
            int r = idx >> 3, c4 = (idx & 7) * 4;
            float4 v = *(const float4*)&Bp[(size_t)(n0 + r) * HC + kb + c4];
            Bs[r][c4] = f2tf(v.x); Bs[r][c4 + 1] = f2tf(v.y);
            Bs[r][c4 + 2] = f2tf(v.z); Bs[r][c4 + 3] = f2tf(v.w);
        }
        __syncthreads();
#pragma unroll
        for (int ks = 0; ks < 4; ++ks) {
            int kk = ks * 8;
            uint32_t af[4][4], bf[4][2];
#pragma unroll
            for (int mi = 0; mi < 4; ++mi) {
                int r = moff + 16 * mi + grp;
                af[mi][0] = As[r][kk + tig];     af[mi][1] = As[r + 8][kk + tig];
                af[mi][2] = As[r][kk + tig + 4]; af[mi][3] = As[r + 8][kk + tig + 4];
            }
#pragma unroll
            for (int ni = 0; ni < 4; ++ni) {
                int c = noff + 8 * ni + grp;
                bf[ni][0] = Bs[c][kk + tig]; bf[ni][1] = Bs[c][kk + tig + 4];
            }
#pragma unroll
            for (int mi = 0; mi < 4; ++mi)
#pragma unroll
                for (int ni = 0; ni < 4; ++ni) MMA_TF32(acc[mi][ni], af[mi], bf[ni]);
        }
        __syncthreads();
    }
#pragma unroll
    for (int mi = 0; mi < 4; ++mi) {
        int r = m0 + moff + 16 * mi + grp;
#pragma unroll
        for (int ni = 0; ni < 4; ++ni) {
            int c = n0 + noff + 8 * ni + 2 * tig;
            *(float2*)&Cp[(size_t)r * P2 + c] = make_float2(acc[mi][ni][0], acc[mi][ni][1]);
            *(float2*)&Cp[(size_t)(r + 8) * P2 + c] = make_float2(acc[mi][ni][2], acc[mi][ni][3]);
        }
    }
}

// ---------------- a = QK^T + 0.5*(rq gather + rk gather) (NT, tf32) ----------------
__global__ void __launch_bounds__(256, 2) a_tc() {
    __shared__ uint32_t As[128][36];
    __shared__ uint32_t Bs[128][36];
    int bh = blockIdx.z, b = bh >> 5, h = bh & 31;
    const float* A  = g_q + (size_t)b * Ss * HC + h * Cc;
    const float* Bp = g_k + (size_t)b * Ss * HC + h * Cc;
    const float* rqb = g_rq + (size_t)bh * (Ss * P2);
    const float* rkb = g_rk + (size_t)bh * (Ss * P2);
    float* Cp = g_a + (size_t)bh * (Ss * Ss);
    int m0 = blockIdx.y * 128, n0 = blockIdx.x * 128;
    int t = threadIdx.x, lane = t & 31, wid = t >> 5;
    int grp = lane >> 2, tig = lane & 3;
    int moff = (wid >> 2) * 64, noff = (wid & 3) * 32;
    float acc[4][4][4] = {};
    for (int kb = 0; kb < Cc; kb += 32) {
#pragma unroll
        for (int i = 0; i < 4; ++i) {
            int idx = t + 256 * i;
            int r = idx >> 3, c4 = (idx & 7) * 4;
            float4 v = *(const float4*)&A[(size_t)(m0 + r) * HC + kb + c4];
            As[r][c4] = f2tf(v.x); As[r][c4 + 1] = f2tf(v.y);
            As[r][c4 + 2] = f2tf(v.z); As[r][c4 + 3] = f2tf(v.w);
        }
#pragma unroll
        for (int i = 0; i < 4; ++i) {
            int idx = t + 256 * i;
            int r = idx >> 3, c4 = (idx & 7) * 4;
            float4 v = *(const float4*)&Bp[(size_t)(n0 + r) * HC + kb + c4];
            Bs[r][c4] = f2tf(v.x); Bs[r][c4 + 1] = f2tf(v.y);
            Bs[r][c4 + 2] = f2tf(v.z); Bs[r][c4 + 3] = f2tf(v.w);
        }
        __syncthreads();
#pragma unroll
        for (int ks = 0; ks < 4; ++ks) {
            int kk = ks * 8;
            uint32_t af[4][4], bf[4][2];
#pragma unroll
            for (int mi = 0; mi < 4; ++mi) {
                int r = moff + 16 * mi + grp;
                af[mi][0] = As[r][kk + tig];     af[mi][1] = As[r + 8][kk + tig];
                af[mi][2] = As[r][kk + tig + 4]; af[mi][3] = As[r + 8][kk + tig + 4];
            }
#pragma unroll
            for (int ni = 0; ni < 4; ++ni) {
                int c = noff + 8 * ni + grp;
                bf[ni][0] = Bs[c][kk + tig]; bf[ni][1] = Bs[c][kk + tig + 4];
            }
#pragma unroll
            for (int mi = 0; mi < 4; ++mi)
#pragma unroll
                for (int ni = 0; ni < 4; ++ni) MMA_TF32(acc[mi][ni], af[mi], bf[ni]);
        }
        __syncthreads();
    }
#pragma unroll
    for (int mi = 0; mi < 4; ++mi) {
        int q0 = m0 + moff + 16 * mi + grp;
#pragma unroll
        for (int ni = 0; ni < 4; ++ni) {
            int kg = n0 + noff + 8 * ni + 2 * tig;
            // rows q0 and q0+8; cols kg and kg+1
            float rq00 = rqb[(size_t)q0 * P2 + kg - q0 + 512];
            float rq01 = rqb[(size_t)q0 * P2 + kg + 1 - q0 + 512];
            float rq10 = rqb[(size_t)(q0 + 8) * P2 + kg - q0 - 8 + 512];
            float rq11 = rqb[(size_t)(q0 + 8) * P2 + kg + 1 - q0 - 8 + 512];
            float rk00 = rkb[(size_t)kg * P2 + q0 - kg + 512];
            float rk01 = rkb[(size_t)(kg + 1) * P2 + q0 - kg - 1 + 512];
            float rk10 = rkb[(size_t)kg * P2 + q0 + 8 - kg + 512];
            float rk11 = rkb[(size_t)(kg + 1) * P2 + q0 + 7 - kg + 512];
            float2 o0 = make_float2(acc[mi][ni][0] + 0.5f * (rq00 + rk00),
                                    acc[mi][ni][1] + 0.5f * (rq01 + rk01));
            float2 o1 = make_float2(acc[mi][ni][2] + 0.5f * (rq10 + rk10),
                                    acc[mi][ni][3] + 0.5f * (rq11 + rk11));
            *(float2*)&Cp[(size_t)q0 * Ss + kg] = o0;
            *(float2*)&Cp[(size_t)(q0 + 8) * Ss + kg] = o1;
        }
    }
}

// ---------------- final: out = a(h) @ w_pair + b_pair + yq + yk  (tf32 mma) ----------------
// per block: (b, q, k-tile of 128). M=128(k), N=128(f), K=32(h)
__global__ void __launch_bounds__(256) final_tc(const float* __restrict__ wpair,
                                                const float* __restrict__ bpair,
                                                float* __restrict__ out) {
    __shared__ uint32_t At[32][136];   // [h][k_local]
    __shared__ uint32_t Ws[32][136];   // [h][f]
    __shared__ float basef[128];
    int k0 = blockIdx.x * 128, q = blockIdx.y, b = blockIdx.z;
    int t = threadIdx.x, lane = t & 31, wid = t >> 5;
    int grp = lane >> 2, tig = lane & 3;
    int moff = (wid >> 2) * 64, noff = (wid & 3) * 32;
#pragma unroll
    for (int i = 0; i < 4; ++i) {
        int idx = t + 256 * i;
        int r = idx >> 5, c4 = (idx & 31) * 4;
        float4 w = *(const float4*)&wpair[r * 128 + c4];
        Ws[r][c4] = f2tf(w.x); Ws[r][c4 + 1] = f2tf(w.y);
        Ws[r][c4 + 2] = f2tf(w.z); Ws[r][c4 + 3] = f2tf(w.w);
        float4 v = *(const float4*)&g_a[(((size_t)(b * 32 + r) * Ss + q) * Ss) + k0 + c4];
        At[r][c4] = f2tf(v.x); At[r][c4 + 1] = f2tf(v.y);
        At[r][c4 + 2] = f2tf(v.z); At[r][c4 + 3] = f2tf(v.w);
    }
    if (t < 128) basef[t] = bpair[t] + g_yq[(size_t)(b * 512 + q) * 128 + t];
    __syncthreads();
    float acc[4][4][4] = {};
#pragma unroll
    for (int ks = 0; ks < 4; ++ks) {
        int kk = ks * 8;
        uint32_t af[4][4], bf[4][2];
#pragma unroll
        for (int mi = 0; mi < 4; ++mi) {
            int r = moff + 16 * mi + grp;
            af[mi][0] = At[kk + tig][r];     af[mi][1] = At[kk + tig][r + 8];
            af[mi][2] = At[kk + tig + 4][r]; af[mi][3] = At[kk + tig + 4][r + 8];
        }
#pragma unroll
        for (int ni = 0; ni < 4; ++ni) {
            int c = noff + 8 * ni + grp;
            bf[ni][0] = Ws[kk + tig][c]; bf[ni][1] = Ws[kk + tig + 4][c];
        }
#pragma unroll
        for (int mi = 0; mi < 4; ++mi)
#pragma unroll
            for (int ni = 0; ni < 4; ++ni) MMA_TF32(acc[mi][ni], af[mi], bf[ni]);
    }
    // epilogue
#pragma unroll
    for (int mi = 0; mi < 4; ++mi) {
        int kl0 = moff + 16 * mi + grp;
        size_t row0 = ((size_t)(b * 512 + q) * 512 + k0 + kl0) * 128;
        size_t row1 = row0 + (size_t)8 * 128;
        const float* yk0 = &g_yk[(size_t)(b * 512 + k0 + kl0) * 128];
        const float* yk1 = yk0 + 8 * 128;
#pragma unroll
        for (int ni = 0; ni < 4; ++ni) {
            int f = noff + 8 * ni + 2 * tig;
            float2 y0 = *(const float2*)&yk0[f];
            float2 y1 = *(const float2*)&yk1[f];
            float2 o0 = make_float2(acc[mi][ni][0] + basef[f] + y0.x,
                                    acc[mi][ni][1] + basef[f + 1] + y0.y);
            float2 o1 = make_float2(acc[mi][ni][2] + basef[f] + y1.x,
                                    acc[mi][ni][3] + basef[f + 1] + y1.y);
            *(float2*)&out[row0 + f] = o0;
            *(float2*)&out[row1 + f] = o1;
        }
    }
}

// ---------------- launcher ----------------
extern "C" void kernel_launch(void* const* d_in, const int* in_sizes, int n_in,
                              void* d_out, int out_size) {
    const float* x        = (const float*)d_in[0];
    const float* scale    = (const float*)d_in[1];
    const float* w_q      = (const float*)d_in[2];
    const float* w_k      = (const float*)d_in[3];
    const float* w_pos    = (const float*)d_in[4];
    const float* b_pos    = (const float*)d_in[5];
    const float* q_r_bias = (const float*)d_in[6];
    const float* k_r_bias = (const float*)d_in[7];
    const float* w_yq     = (const float*)d_in[8];
    const float* w_yk     = (const float*)d_in[9];
    const float* w_pair   = (const float*)d_in[10];
    const float* b_pair   = (const float*)d_in[11];
    float* out = (float*)d_out;

    float *p_xp, *p_g, *p_q, *p_k, *p_ypart;
    cudaGetSymbolAddress((void**)&p_xp, g_xp);
    cudaGetSymbolAddress((void**)&p_g, g_g);
    cudaGetSymbolAddress((void**)&p_q, g_q);
    cudaGetSymbolAddress((void**)&p_k, g_k);
    cudaGetSymbolAddress((void**)&p_ypart, g_ypart);

    init_cw_kernel<<<1, 32>>>();
    pool_norm_kernel<<<1024, 384>>>(x, scale);
    suffix_kernel<<<16, 256>>>(w_pos);
    posenc_kernel<<<dim3(1024, 8), 512>>>(b_pos);
    // q, k projections: M=1024, N=4096, K=1536 (tf32 tensor cores)
    gemm_nn_tc<<<dim3(32, 8, 1), 256>>>(p_xp, w_q, p_q, Dd, HC, HC, Dd, 0);
    gemm_nn_tc<<<dim3(32, 8, 1), 256>>>(p_xp, w_k, p_k, Dd, HC, HC, Dd, 0);
    // y projections via k-split (8 slices of 192)
    gemm_nn_tc<<<dim3(1, 8, 8), 256>>>(p_g, w_yq, p_ypart, Dd, PAIRF, PAIRF, 192, 131072LL);
    gemm_nn_tc<<<dim3(1, 8, 8), 256>>>(p_g, w_yk, p_ypart + 8 * 131072, Dd, PAIRF, PAIRF, 192, 131072LL);
    reduce_y_kernel<<<512, 256>>>();
    // rel logits: 128 gemms of 512x1024x128
    rel_tc<<<dim3(8, 4, 128), 256>>>(q_r_bias, k_r_bias);
    // a = QK^T + 0.5*(rq+rk): 64 gemms of 512x512x128
    a_tc<<<dim3(4, 4, 64), 256>>>();
    // head->pair projection + biases + y terms (tensor cores, memory-bound)
    final_tc<<<dim3(4, 512, 2), 256>>>(w_pair, b_pair, out);
}

// round 3
// speedup vs baseline: 3.0068x; 1.1856x over previous
#include <cuda_runtime.h>
#include <math.h>
#include <stdint.h>

#define Bb 2
#define SFULL 8192
#define Dd 1536
#define Ss 512
#define Hh 32
#define Cc 128
#define HC 4096
#define Ff 32
#define PAIRF 128
#define P2 1024

// ---------------- scratch ----------------
__device__ float g_xp[Bb*Ss*Dd];
__device__ float g_g [Bb*Ss*Dd];
__device__ float g_q [Bb*Ss*HC];
__device__ float g_k [Bb*Ss*HC];
__device__ float g_pos[P2*HC];
__device__ float g_sufq[Ff*HC];
__device__ float g_sufs[Ff*HC];
__device__ float g_cw[Ff];
__device__ int   g_fmin[513];
__device__ float g_yq[Bb*Ss*PAIRF];
__device__ float g_yk[Bb*Ss*PAIRF];
__device__ float g_ypart[16*Bb*Ss*PAIRF];
__device__ float g_rq[(size_t)Bb*Hh*Ss*P2];
__device__ float g_rk[(size_t)Bb*Hh*Ss*P2];
__device__ float g_a [(size_t)Bb*Hh*Ss*Ss];

// ---------------- helpers ----------------
__device__ __forceinline__ uint32_t f2tf(float f) {
    uint32_t u;
    asm("cvt.rna.tf32.f32 %0, %1;" : "=r"(u) : "f"(f));
    return u;
}

#define MMA_TF32(d, a, b) asm volatile( \
    "mma.sync.aligned.m16n8k8.row.col.f32.tf32.tf32.f32 " \
    "{%0,%1,%2,%3}, {%4,%5,%6,%7}, {%8,%9}, {%0,%1,%2,%3};\n" \
    : "+f"((d)[0]), "+f"((d)[1]), "+f"((d)[2]), "+f"((d)[3]) \
    : "r"((a)[0]), "r"((a)[1]), "r"((a)[2]), "r"((a)[3]), \
      "r"((b)[0]), "r"((b)[1]))

__device__ __forceinline__ void cpa16(void* dst, const void* src) {
    uint32_t d = (uint32_t)__cvta_generic_to_shared(dst);
    asm volatile("cp.async.ca.shared.global [%0], [%1], 16;\n" :: "r"(d), "l"(src));
}
#define CPCOMMIT() asm volatile("cp.async.commit_group;\n")
#define CPWAIT0()  asm volatile("cp.async.wait_group 0;\n")

// ---------------- small init kernels ----------------
__global__ void init_cw_kernel() {
    int f = threadIdx.x;
    if (f < Ff)
        g_cw[f] = (float)((double)f + exp(log(481.0) * ((double)f / 32.0)));
}

__global__ void fmin_kernel() {
    int d = blockIdx.x * 128 + threadIdx.x;
    if (d <= 512) {
        int fm = 32;
        for (int f = 31; f >= 0; --f)
            if (g_cw[f] > (float)d) fm = f;
        g_fmin[d] = fm;
    }
}

// pool(16) + RMSNorm + gelu
__global__ void __launch_bounds__(384) pool_norm_kernel(const float* __restrict__ x,
                                                        const float* __restrict__ scale) {
    int row = blockIdx.x;
    int t = threadIdx.x;
    const float* xr = x + (size_t)row * 16 * Dd;
    float pooled[4];
    float ss = 0.f;
#pragma unroll
    for (int u = 0; u < 4; ++u) {
        int d = t + u * 384;
        float s = 0.f;
#pragma unroll
        for (int j = 0; j < 16; ++j) s += xr[(size_t)j * Dd + d];
        s *= 0.0625f;
        pooled[u] = s;
        ss += s * s;
    }
    __shared__ float red[13];
#pragma unroll
    for (int o = 16; o; o >>= 1) ss += __shfl_xor_sync(0xffffffffu, ss, o);
    if ((t & 31) == 0) red[t >> 5] = ss;
    __syncthreads();
    if (t == 0) {
        float tot = 0.f;
        for (int i = 0; i < 12; ++i) tot += red[i];
        red[12] = rsqrtf(tot * (1.f / 1536.f) + 1e-5f);
    }
    __syncthreads();
    float inv = red[12];
#pragma unroll
    for (int u = 0; u < 4; ++u) {
        int d = t + u * 384;
        float v = pooled[u] * inv * scale[d];
        g_xp[(size_t)row * Dd + d] = v;
        float v3 = v * v * v;
        float gl = 0.5f * v * (1.f + tanhf(0.7978845608028654f * (v + 0.044715f * v3)));
        g_g[(size_t)row * Dd + d] = gl;
    }
}

__global__ void suffix_kernel(const float* __restrict__ wpos) {
    int hc = blockIdx.x * 256 + threadIdx.x;
    float aq = 0.f, as = 0.f;
    for (int f = Ff - 1; f >= 0; --f) {
        aq += wpos[f * HC + hc];
        as += wpos[(Ff + f) * HC + hc];
        g_sufq[f * HC + hc] = aq;
        g_sufs[f * HC + hc] = as;
    }
}

// pos encoding: table lookup + vectorized copy
__global__ void __launch_bounds__(256) posenc_kernel(const float* __restrict__ bpos) {
    int p = blockIdx.x;
    int hc4 = (blockIdx.y * 256 + threadIdx.x) * 4;
    int dist = (p >= 512) ? p - 512 : 512 - p;
    int fm = g_fmin[dist];
    float4 v = *(const float4*)&bpos[hc4];
    if (fm < 32) {
        float sg = (p > 512) ? 1.f : ((p < 512) ? -1.f : 0.f);
        float4 a = *(const float4*)&g_sufq[fm * HC + hc4];
        float4 s = *(const float4*)&g_sufs[fm * HC + hc4];
        v.x += a.x + sg * s.x; v.y += a.y + sg * s.y;
        v.z += a.z + sg * s.z; v.w += a.w + sg * s.w;
    }
    *(float4*)&g_pos[(size_t)p * HC + hc4] = v;
}

__global__ void reduce_y_kernel() {
    int i = blockIdx.x * 256 + threadIdx.x;
    float sq = 0.f, sk = 0.f;
#pragma unroll
    for (int s = 0; s < 8; ++s) {
        sq += g_ypart[s * 131072 + i];
        sk += g_ypart[(8 + s) * 131072 + i];
    }
    g_yq[i] = sq;
    g_yk[i] = sk;
}

// ---------------- pipelined tf32 GEMM (NN): C = A[M,K] @ B[K,N] ----------------
__global__ void __launch_bounds__(256, 2) gemm_nn_tc(const float* __restrict__ A,
                                                     const float* __restrict__ Bm,
                                                     float* __restrict__ C,
                                                     int lda, int ldb, int ldc,
                                                     int ksz, long long coffs) {
    __shared__ float As[2][128][36];
    __shared__ float Bs[2][32][136];
    int m0 = blockIdx.y * 128, n0 = blockIdx.x * 128;
    C += (size_t)blockIdx.z * (size_t)coffs;
    int kstart = blockIdx.z * ksz;
    int t = threadIdx.x, lane = t & 31, wid = t >> 5;
    int grp = lane >> 2, tig = lane & 3;
    int moff = (wid >> 2) * 64, noff = (wid & 3) * 32;
    float acc[4][4][4] = {};

    int nk = ksz >> 5;
    // prologue
    {
        int kb = kstart;
#pragma unroll
        for (int i = 0; i < 4; ++i) {
            int idx = t + 256 * i;
            int r = idx >> 3, c4 = (idx & 7) * 4;
            cpa16(&As[0][r][c4], &A[(size_t)(m0 + r) * lda + kb + c4]);
        }
#pragma unroll
        for (int i = 0; i < 4; ++i) {
            int idx = t + 256 * i;
            int r = idx >> 5, c4 = (idx & 31) * 4;
            cpa16(&Bs[0][r][c4], &Bm[(size_t)(kb + r) * ldb + n0 + c4]);
        }
        CPCOMMIT();
    }
    for (int ib = 0; ib < nk; ++ib) {
        CPWAIT0();
        __syncthreads();
        if (ib + 1 < nk) {
            int kb = kstart + (ib + 1) * 32;
            int st = (ib + 1) & 1;
#pragma unroll
            for (int i = 0; i < 4; ++i) {
                int idx = t + 256 * i;
                int r = idx >> 3, c4 = (idx & 7) * 4;
                cpa16(&As[st][r][c4], &A[(size_t)(m0 + r) * lda + kb + c4]);
            }
#pragma unroll
            for (int i = 0; i < 4; ++i) {
                int idx = t + 256 * i;
                int r = idx >> 5, c4 = (idx & 31) * 4;
                cpa16(&Bs[st][r][c4], &Bm[(size_t)(kb + r) * ldb + n0 + c4]);
            }
            CPCOMMIT();
        }
        int st = ib & 1;
#pragma unroll
        for (int ks = 0; ks < 4; ++ks) {
            int kk = ks * 8;
            uint32_t af[4][4], bf[4][2];
#pragma unroll
            for (int mi = 0; mi < 4; ++mi) {
                int r = moff + 16 * mi + grp;
                af[mi][0] = f2tf(As[st][r][kk + tig]);
                af[mi][1] = f2tf(As[st][r + 8][kk + tig]);
                af[mi][2] = f2tf(As[st][r][kk + tig + 4]);
                af[mi][3] = f2tf(As[st][r + 8][kk + tig + 4]);
            }
#pragma unroll
            for (int ni = 0; ni < 4; ++ni) {
                int c = noff + 8 * ni + grp;
                bf[ni][0] = f2tf(Bs[st][kk + tig][c]);
                bf[ni][1] = f2tf(Bs[st][kk + tig + 4][c]);
            }
#pragma unroll
            for (int mi = 0; mi < 4; ++mi)
#pragma unroll
                for (int ni = 0; ni < 4; ++ni) MMA_TF32(acc[mi][ni], af[mi], bf[ni]);
        }
        __syncthreads();
    }
#pragma unroll
    for (int mi = 0; mi < 4; ++mi) {
        int r = m0 + moff + 16 * mi + grp;
#pragma unroll
        for (int ni = 0; ni < 4; ++ni) {
            int c = n0 + noff + 8 * ni + 2 * tig;
            *(float2*)&C[(size_t)r * ldc + c] = make_float2(acc[mi][ni][0], acc[mi][ni][1]);
            *(float2*)&C[(size_t)(r + 8) * ldc + c] = make_float2(acc[mi][ni][2], acc[mi][ni][3]);
        }
    }
}

// ---------------- rel logits (NT), band-restricted, pipelined ----------------
__global__ void __launch_bounds__(256, 2) rel_tc(const float* __restrict__ qrb,
                                                 const float* __restrict__ krb) {
    __shared__ float As[2][128][36];
    __shared__ float Bs[2][128][36];
    __shared__ float rbs[128];
    int z = blockIdx.z;
    int side = z >> 6, bh = z & 63, b = bh >> 5, h = bh & 31;
    const float* A = (side ? g_k : g_q) + (size_t)b * Ss * HC + h * Cc;
    const float* rb = (side ? krb : qrb) + h * Cc;
    const float* Bp = g_pos + h * Cc;
    float* Cp = (side ? g_rk : g_rq) + (size_t)bh * (Ss * P2);
    int my = blockIdx.y;
    int m0 = my * 128;
    int n0 = (blockIdx.x + 3 - my) * 128;   // band restriction: only needed p tiles
    int t = threadIdx.x, lane = t & 31, wid = t >> 5;
    int grp = lane >> 2, tig = lane & 3;
    int moff = (wid >> 2) * 64, noff = (wid & 3) * 32;
    if (t < 128) rbs[t] = rb[t];
    float acc[4][4][4] = {};
    // prologue
    {
#pragma unroll
        for (int i = 0; i < 4; ++i) {
            int idx = t + 256 * i;
            int r = idx >> 3, c4 = (idx & 7) * 4;
            cpa16(&As[0][r][c4], &A[(size_t)(m0 + r) * HC + c4]);
            cpa16(&Bs[0][r][c4], &Bp[(size_t)(n0 + r) * HC + c4]);
        }
        CPCOMMIT();
    }
    for (int ib = 0; ib < 4; ++ib) {
        CPWAIT0();
        __syncthreads();
        if (ib < 3) {
            int kb = (ib + 1) * 32;
            int st = (ib + 1) & 1;
#pragma unroll
            for (int i = 0; i < 4; ++i) {
                int idx = t + 256 * i;
                int r = idx >> 3, c4 = (idx & 7) * 4;
                cpa16(&As[st][r][c4], &A[(size_t)(m0 + r) * HC + kb + c4]);
                cpa16(&Bs[st][r][c4], &Bp[(size_t)(n0 + r) * HC + kb + c4]);
            }
            CPCOMMIT();
        }
        int st = ib & 1;
        int kbase = ib * 32;
#pragma unroll
        for (int ks = 0; ks < 4; ++ks) {
            int kk = ks * 8;
            float b0 = rbs[kbase + kk + tig], b1 = rbs[kbase + kk + tig + 4];
            uint32_t af[4][4], bf[4][2];
#pragma unroll
            for (int mi = 0; mi < 4; ++mi) {
                int r = moff + 16 * mi + grp;
                af[mi][0] = f2tf(As[st][r][kk + tig] + b0);
                af[mi][1] = f2tf(As[st][r + 8][kk + tig] + b0);
                af[mi][2] = f2tf(As[st][r][kk + tig + 4] + b1);
                af[mi][3] = f2tf(As[st][r + 8][kk + tig + 4] + b1);
            }
#pragma unroll
            for (int ni = 0; ni < 4; ++ni) {
                int c = noff + 8 * ni + grp;
                bf[ni][0] = f2tf(Bs[st][c][kk + tig]);
                bf[ni][1] = f2tf(Bs[st][c][kk + tig + 4]);
            }
#pragma unroll
            for (int mi = 0; mi < 4; ++mi)
#pragma unroll
                for (int ni = 0; ni < 4; ++ni) MMA_TF32(acc[mi][ni], af[mi], bf[ni]);
        }
        __syncthreads();
    }
#pragma unroll
    for (int mi = 0; mi < 4; ++mi) {
        int r = m0 + moff + 16 * mi + grp;
#pragma unroll
        for (int ni = 0; ni < 4; ++ni) {
            int c = n0 + noff + 8 * ni + 2 * tig;
            *(float2*)&Cp[(size_t)r * P2 + c] = make_float2(acc[mi][ni][0], acc[mi][ni][1]);
            *(float2*)&Cp[(size_t)(r + 8) * P2 + c] = make_float2(acc[mi][ni][2], acc[mi][ni][3]);
        }
    }
}

// ---------------- a = QK^T + 0.5*(rq + rk gathers) (NT), pipelined ----------------
__global__ void __launch_bounds__(256, 2) a_tc() {
    __shared__ float As[2][128][36];
    __shared__ float Bs[2][128][36];
    int bh = blockIdx.z, b = bh >> 5, h = bh & 31;
    const float* A  = g_q + (size_t)b * Ss * HC + h * Cc;
    const float* Bp = g_k + (size_t)b * Ss * HC + h * Cc;
    const float* rqb = g_rq + (size_t)bh * (Ss * P2);
    const float* rkb = g_rk + (size_t)bh * (Ss * P2);
    float* Cp = g_a + (size_t)bh * (Ss * Ss);
    int m0 = blockIdx.y * 128, n0 = blockIdx.x * 128;
    int t = threadIdx.x, lane = t & 31, wid = t >> 5;
    int grp = lane >> 2, tig = lane & 3;
    int moff = (wid >> 2) * 64, noff = (wid & 3) * 32;
    float acc[4][4][4] = {};
    {
#pragma unroll
        for (int i = 0; i < 4; ++i) {
            int idx = t + 256 * i;
            int r = idx >> 3, c4 = (idx & 7) * 4;
            cpa16(&As[0][r][c4], &A[(size_t)(m0 + r) * HC + c4]);
            cpa16(&Bs[0][r][c4], &Bp[(size_t)(n0 + r) * HC + c4]);
        }
        CPCOMMIT();
    }
    for (int ib = 0; ib < 4; ++ib) {
        CPWAIT0();
        __syncthreads();
        if (ib < 3) {
            int kb = (ib + 1) * 32;
            int st = (ib + 1) & 1;
#pragma unroll
            for (int i = 0; i < 4; ++i) {
                int idx = t + 256 * i;
                int r = idx >> 3, c4 = (idx & 7) * 4;
                cpa16(&As[st][r][c4], &A[(size_t)(m0 + r) * HC + kb + c4]);
                cpa16(&Bs[st][r][c4], &Bp[(size_t)(n0 + r) * HC + kb + c4]);
            }
            CPCOMMIT();
        }
        int st = ib & 1;
#pragma unroll
        for (int ks = 0; ks < 4; ++ks) {
            int kk = ks * 8;
            uint32_t af[4][4], bf[4][2];
#pragma unroll
            for (int mi = 0; mi < 4; ++mi) {
                int r = moff + 16 * mi + grp;
                af[mi][0] = f2tf(As[st][r][kk + tig]);
                af[mi][1] = f2tf(As[st][r + 8][kk + tig]);
                af[mi][2] = f2tf(As[st][r][kk + tig + 4]);
                af[mi][3] = f2tf(As[st][r + 8][kk + tig + 4]);
            }
#pragma unroll
            for (int ni = 0; ni < 4; ++ni) {
                int c = noff + 8 * ni + grp;
                bf[ni][0] = f2tf(Bs[st][c][kk + tig]);
                bf[ni][1] = f2tf(Bs[st][c][kk + tig + 4]);
            }
#pragma unroll
            for (int mi = 0; mi < 4; ++mi)
#pragma unroll
                for (int ni = 0; ni < 4; ++ni) MMA_TF32(acc[mi][ni], af[mi], bf[ni]);
        }
        __syncthreads();
    }
#pragma unroll
    for (int mi = 0; mi < 4; ++mi) {
        int q0 = m0 + moff + 16 * mi + grp;
#pragma unroll
        for (int ni = 0; ni < 4; ++ni) {
            int kg = n0 + noff + 8 * ni + 2 * tig;
            float rq00 = rqb[(size_t)q0 * P2 + kg - q0 + 512];
            float rq01 = rqb[(size_t)q0 * P2 + kg + 1 - q0 + 512];
            float rq10 = rqb[(size_t)(q0 + 8) * P2 + kg - q0 - 8 + 512];
            float rq11 = rqb[(size_t)(q0 + 8) * P2 + kg + 1 - q0 - 8 + 512];
            float rk00 = rkb[(size_t)kg * P2 + q0 - kg + 512];
            float rk01 = rkb[(size_t)(kg + 1) * P2 + q0 - kg - 1 + 512];
            float rk10 = rkb[(size_t)kg * P2 + q0 + 8 - kg + 512];
            float rk11 = rkb[(size_t)(kg + 1) * P2 + q0 + 7 - kg + 512];
            float2 o0 = make_float2(acc[mi][ni][0] + 0.5f * (rq00 + rk00),
                                    acc[mi][ni][1] + 0.5f * (rq01 + rk01));
            float2 o1 = make_float2(acc[mi][ni][2] + 0.5f * (rq10 + rk10),
                                    acc[mi][ni][3] + 0.5f * (rq11 + rk11));
            *(float2*)&Cp[(size_t)q0 * Ss + kg] = o0;
            *(float2*)&Cp[(size_t)(q0 + 8) * Ss + kg] = o1;
        }
    }
}

// ---------------- final: out = a(h) @ w_pair + b_pair + yq + yk ----------------
__global__ void __launch_bounds__(256) final_tc(const float* __restrict__ wpair,
                                                const float* __restrict__ bpair,
                                                float* __restrict__ out) {
    __shared__ uint32_t At[32][136];
    __shared__ uint32_t Ws[32][136];
    __shared__ float basef[128];
    int k0 = blockIdx.x * 128, q = blockIdx.y, b = blockIdx.z;
    int t = threadIdx.x, lane = t & 31, wid = t >> 5;
    int grp = lane >> 2, tig = lane & 3;
    int moff = (wid >> 2) * 64, noff = (wid & 3) * 32;
#pragma unroll
    for (int i = 0; i < 4; ++i) {
        int idx = t + 256 * i;
        int r = idx >> 5, c4 = (idx & 31) * 4;
        float4 w = *(const float4*)&wpair[r * 128 + c4];
        Ws[r][c4] = f2tf(w.x); Ws[r][c4 + 1] = f2tf(w.y);
        Ws[r][c4 + 2] = f2tf(w.z); Ws[r][c4 + 3] = f2tf(w.w);
        float4 v = *(const float4*)&g_a[(((size_t)(b * 32 + r) * Ss + q) * Ss) + k0 + c4];
        At[r][c4] = f2tf(v.x); At[r][c4 + 1] = f2tf(v.y);
        At[r][c4 + 2] = f2tf(v.z); At[r][c4 + 3] = f2tf(v.w);
    }
    if (t < 128) basef[t] = bpair[t] + g_yq[(size_t)(b * 512 + q) * 128 + t];
    __syncthreads();
    float acc[4][4][4] = {};
#pragma unroll
    for (int ks = 0; ks < 4; ++ks) {
        int kk = ks * 8;
        uint32_t af[4][4], bf[4][2];
#pragma unroll
        for (int mi = 0; mi < 4; ++mi) {
            int r = moff + 16 * mi + grp;
            af[mi][0] = At[kk + tig][r];     af[mi][1] = At[kk + tig][r + 8];
            af[mi][2] = At[kk + tig + 4][r]; af[mi][3] = At[kk + tig + 4][r + 8];
        }
#pragma unroll
        for (int ni = 0; ni < 4; ++ni) {
            int c = noff + 8 * ni + grp;
            bf[ni][0] = Ws[kk + tig][c]; bf[ni][1] = Ws[kk + tig + 4][c];
        }
#pragma unroll
        for (int mi = 0; mi < 4; ++mi)
#pragma unroll
            for (int ni = 0; ni < 4; ++ni) MMA_TF32(acc[mi][ni], af[mi], bf[ni]);
    }
#pragma unroll
    for (int mi = 0; mi < 4; ++mi) {
        int kl0 = moff + 16 * mi + grp;
        size_t row0 = ((size_t)(b * 512 + q) * 512 + k0 + kl0) * 128;
        size_t row1 = row0 + (size_t)8 * 128;
        const float* yk0 = &g_yk[(size_t)(b * 512 + k0 + kl0) * 128];
        const float* yk1 = yk0 + 8 * 128;
#pragma unroll
        for (int ni = 0; ni < 4; ++ni) {
            int f = noff + 8 * ni + 2 * tig;
            float2 y0 = *(const float2*)&yk0[f];
            float2 y1 = *(const float2*)&yk1[f];
            float2 o0 = make_float2(acc[mi][ni][0] + basef[f] + y0.x,
                                    acc[mi][ni][1] + basef[f + 1] + y0.y);
            float2 o1 = make_float2(acc[mi][ni][2] + basef[f] + y1.x,
                                    acc[mi][ni][3] + basef[f + 1] + y1.y);
            *(float2*)&out[row0 + f] = o0;
            *(float2*)&out[row1 + f] = o1;
        }
    }
}

// ---------------- launcher ----------------
extern "C" void kernel_launch(void* const* d_in, const int* in_sizes, int n_in,
                              void* d_out, int out_size) {
    const float* x        = (const float*)d_in[0];
    const float* scale    = (const float*)d_in[1];
    const float* w_q      = (const float*)d_in[2];
    const float* w_k      = (const float*)d_in[3];
    const float* w_pos    = (const float*)d_in[4];
    const float* b_pos    = (const float*)d_in[5];
    const float* q_r_bias = (const float*)d_in[6];
    const float* k_r_bias = (const float*)d_in[7];
    const float* w_yq     = (const float*)d_in[8];
    const float* w_yk     = (const float*)d_in[9];
    const float* w_pair   = (const float*)d_in[10];
    const float* b_pair   = (const float*)d_in[11];
    float* out = (float*)d_out;

    float *p_xp, *p_g, *p_q, *p_k, *p_ypart;
    cudaGetSymbolAddress((void**)&p_xp, g_xp);
    cudaGetSymbolAddress((void**)&p_g, g_g);
    cudaGetSymbolAddress((void**)&p_q, g_q);
    cudaGetSymbolAddress((void**)&p_k, g_k);
    cudaGetSymbolAddress((void**)&p_ypart, g_ypart);

    init_cw_kernel<<<1, 32>>>();
    fmin_kernel<<<5, 128>>>();
    pool_norm_kernel<<<1024, 384>>>(x, scale);
    suffix_kernel<<<16, 256>>>(w_pos);
    posenc_kernel<<<dim3(1024, 4), 256>>>(b_pos);
    // q, k projections: M=1024, N=4096, K=1536
    gemm_nn_tc<<<dim3(32, 8, 1), 256>>>(p_xp, w_q, p_q, Dd, HC, HC, Dd, 0);
    gemm_nn_tc<<<dim3(32, 8, 1), 256>>>(p_xp, w_k, p_k, Dd, HC, HC, Dd, 0);
    // y projections via k-split (8 slices of 192)
    gemm_nn_tc<<<dim3(1, 8, 8), 256>>>(p_g, w_yq, p_ypart, Dd, PAIRF, PAIRF, 192, 131072LL);
    gemm_nn_tc<<<dim3(1, 8, 8), 256>>>(p_g, w_yk, p_ypart + 8 * 131072, Dd, PAIRF, PAIRF, 192, 131072LL);
    reduce_y_kernel<<<512, 256>>>();
    // rel logits: band-restricted (5 of 8 p-tiles per q-tile)
    rel_tc<<<dim3(5, 4, 128), 256>>>(q_r_bias, k_r_bias);
    // a = QK^T + 0.5*(rq+rk)
    a_tc<<<dim3(4, 4, 64), 256>>>();
    // head->pair projection + biases + y terms
    final_tc<<<dim3(4, 512, 2), 256>>>(w_pair, b_pair, out);
}

// round 4
// speedup vs baseline: 3.0087x; 1.0007x over previous
#include <cuda_runtime.h>
#include <math.h>
#include <stdint.h>

#define Bb 2
#define SFULL 8192
#define Dd 1536
#define Ss 512
#define Hh 32
#define Cc 128
#define HC 4096
#define Ff 32
#define PAIRF 128
#define P2 1024

// ---------------- scratch ----------------
__device__ float g_xp[Bb*Ss*Dd];
__device__ float g_g [Bb*Ss*Dd];
__device__ float g_q [Bb*Ss*HC];
__device__ float g_k [Bb*Ss*HC];
__device__ float g_pos[P2*HC];
__device__ float g_sufq[Ff*HC];
__device__ float g_sufs[Ff*HC];
__device__ float g_cw[Ff];
__device__ int   g_fmin[513];
__device__ float g_yq[Bb*Ss*PAIRF];
__device__ float g_yk[Bb*Ss*PAIRF];
__device__ float g_ypart[16*Bb*Ss*PAIRF];
__device__ float g_rq[(size_t)Bb*Hh*Ss*P2];
__device__ float g_rk[(size_t)Bb*Hh*Ss*P2];
__device__ float g_a [(size_t)Bb*Hh*Ss*Ss];

// ---------------- helpers ----------------
__device__ __forceinline__ uint32_t f2tf(float f) {
    uint32_t u;
    asm("cvt.rna.tf32.f32 %0, %1;" : "=r"(u) : "f"(f));
    return u;
}

#define MMA_TF32(d, a, b) asm volatile( \
    "mma.sync.aligned.m16n8k8.row.col.f32.tf32.tf32.f32 " \
    "{%0,%1,%2,%3}, {%4,%5,%6,%7}, {%8,%9}, {%0,%1,%2,%3};\n" \
    : "+f"((d)[0]), "+f"((d)[1]), "+f"((d)[2]), "+f"((d)[3]) \
    : "r"((a)[0]), "r"((a)[1]), "r"((a)[2]), "r"((a)[3]), \
      "r"((b)[0]), "r"((b)[1]))

__device__ __forceinline__ void cpa16(void* dst, const void* src) {
    uint32_t d = (uint32_t)__cvta_generic_to_shared(dst);
    asm volatile("cp.async.ca.shared.global [%0], [%1], 16;\n" :: "r"(d), "l"(src));
}
#define CPCOMMIT() asm volatile("cp.async.commit_group;\n")
#define CPWAIT0()  asm volatile("cp.async.wait_group 0;\n")

// ---------------- small init kernels ----------------
__global__ void init_cw_kernel() {
    int f = threadIdx.x;
    if (f < Ff)
        g_cw[f] = (float)((double)f + exp(log(481.0) * ((double)f / 32.0)));
}

__global__ void fmin_kernel() {
    int d = blockIdx.x * 128 + threadIdx.x;
    if (d <= 512) {
        int fm = 32;
        for (int f = 31; f >= 0; --f)
            if (g_cw[f] > (float)d) fm = f;
        g_fmin[d] = fm;
    }
}

// pool(16) + RMSNorm + gelu
__global__ void __launch_bounds__(384) pool_norm_kernel(const float* __restrict__ x,
                                                        const float* __restrict__ scale) {
    int row = blockIdx.x;
    int t = threadIdx.x;
    const float* xr = x + (size_t)row * 16 * Dd;
    float pooled[4];
    float ss = 0.f;
#pragma unroll
    for (int u = 0; u < 4; ++u) {
        int d = t + u * 384;
        float s = 0.f;
#pragma unroll
        for (int j = 0; j < 16; ++j) s += xr[(size_t)j * Dd + d];
        s *= 0.0625f;
        pooled[u] = s;
        ss += s * s;
    }
    __shared__ float red[13];
#pragma unroll
    for (int o = 16; o; o >>= 1) ss += __shfl_xor_sync(0xffffffffu, ss, o);
    if ((t & 31) == 0) red[t >> 5] = ss;
    __syncthreads();
    if (t == 0) {
        float tot = 0.f;
        for (int i = 0; i < 12; ++i) tot += red[i];
        red[12] = rsqrtf(tot * (1.f / 1536.f) + 1e-5f);
    }
    __syncthreads();
    float inv = red[12];
#pragma unroll
    for (int u = 0; u < 4; ++u) {
        int d = t + u * 384;
        float v = pooled[u] * inv * scale[d];
        g_xp[(size_t)row * Dd + d] = v;
        float v3 = v * v * v;
        float gl = 0.5f * v * (1.f + tanhf(0.7978845608028654f * (v + 0.044715f * v3)));
        g_g[(size_t)row * Dd + d] = gl;
    }
}

__global__ void suffix_kernel(const float* __restrict__ wpos) {
    int hc = blockIdx.x * 256 + threadIdx.x;
    float aq = 0.f, as = 0.f;
    for (int f = Ff - 1; f >= 0; --f) {
        aq += wpos[f * HC + hc];
        as += wpos[(Ff + f) * HC + hc];
        g_sufq[f * HC + hc] = aq;
        g_sufs[f * HC + hc] = as;
    }
}

// pos encoding: table lookup + vectorized copy
__global__ void __launch_bounds__(256) posenc_kernel(const float* __restrict__ bpos) {
    int p = blockIdx.x;
    int hc4 = (blockIdx.y * 256 + threadIdx.x) * 4;
    int dist = (p >= 512) ? p - 512 : 512 - p;
    int fm = g_fmin[dist];
    float4 v = *(const float4*)&bpos[hc4];
    if (fm < 32) {
        float sg = (p > 512) ? 1.f : ((p < 512) ? -1.f : 0.f);
        float4 a = *(const float4*)&g_sufq[fm * HC + hc4];
        float4 s = *(const float4*)&g_sufs[fm * HC + hc4];
        v.x += a.x + sg * s.x; v.y += a.y + sg * s.y;
        v.z += a.z + sg * s.z; v.w += a.w + sg * s.w;
    }
    *(float4*)&g_pos[(size_t)p * HC + hc4] = v;
}

__global__ void reduce_y_kernel() {
    int i = blockIdx.x * 256 + threadIdx.x;
    float sq = 0.f, sk = 0.f;
#pragma unroll
    for (int s = 0; s < 8; ++s) {
        sq += g_ypart[s * 131072 + i];
        sk += g_ypart[(8 + s) * 131072 + i];
    }
    g_yq[i] = sq;
    g_yk[i] = sk;
}

// ---------------- pipelined tf32 GEMM (NN): C = A[M,K] @ B[K,N] ----------------
__global__ void __launch_bounds__(256, 2) gemm_nn_tc(const float* __restrict__ A,
                                                     const float* __restrict__ Bm,
                                                     float* __restrict__ C,
                                                     int lda, int ldb, int ldc,
                                                     int ksz, long long coffs) {
    __shared__ float As[2][128][36];
    __shared__ float Bs[2][32][136];
    int m0 = blockIdx.y * 128, n0 = blockIdx.x * 128;
    C += (size_t)blockIdx.z * (size_t)coffs;
    int kstart = blockIdx.z * ksz;
    int t = threadIdx.x, lane = t & 31, wid = t >> 5;
    int grp = lane >> 2, tig = lane & 3;
    int moff = (wid >> 2) * 64, noff = (wid & 3) * 32;
    float acc[4][4][4] = {};

    int nk = ksz >> 5;
    // prologue
    {
        int kb = kstart;
#pragma unroll
        for (int i = 0; i < 4; ++i) {
            int idx = t + 256 * i;
            int r = idx >> 3, c4 = (idx & 7) * 4;
            cpa16(&As[0][r][c4], &A[(size_t)(m0 + r) * lda + kb + c4]);
        }
#pragma unroll
        for (int i = 0; i < 4; ++i) {
            int idx = t + 256 * i;
            int r = idx >> 5, c4 = (idx & 31) * 4;
            cpa16(&Bs[0][r][c4], &Bm[(size_t)(kb + r) * ldb + n0 + c4]);
        }
        CPCOMMIT();
    }
    for (int ib = 0; ib < nk; ++ib) {
        CPWAIT0();
        __syncthreads();
        if (ib + 1 < nk) {
            int kb = kstart + (ib + 1) * 32;
            int st = (ib + 1) & 1;
#pragma unroll
            for (int i = 0; i < 4; ++i) {
                int idx = t + 256 * i;
                int r = idx >> 3, c4 = (idx & 7) * 4;
                cpa16(&As[st][r][c4], &A[(size_t)(m0 + r) * lda + kb + c4]);
            }
#pragma unroll
            for (int i = 0; i < 4; ++i) {
                int idx = t + 256 * i;
                int r = idx >> 5, c4 = (idx & 31) * 4;
                cpa16(&Bs[st][r][c4], &Bm[(size_t)(kb + r) * ldb + n0 + c4]);
            }
            CPCOMMIT();
        }
        int st = ib & 1;
#pragma unroll
        for (int ks = 0; ks < 4; ++ks) {
            int kk = ks * 8;
            uint32_t af[4][4], bf[4][2];
#pragma unroll
            for (int mi = 0; mi < 4; ++mi) {
                int r = moff + 16 * mi + grp;
                af[mi][0] = f2tf(As[st][r][kk + tig]);
                af[mi][1] = f2tf(As[st][r + 8][kk + tig]);
                af[mi][2] = f2tf(As[st][r][kk + tig + 4]);
                af[mi][3] = f2tf(As[st][r + 8][kk + tig + 4]);
            }
#pragma unroll
            for (int ni = 0; ni < 4; ++ni) {
                int c = noff + 8 * ni + grp;
                bf[ni][0] = f2tf(Bs[st][kk + tig][c]);
                bf[ni][1] = f2tf(Bs[st][kk + tig + 4][c]);
            }
#pragma unroll
            for (int mi = 0; mi < 4; ++mi)
#pragma unroll
                for (int ni = 0; ni < 4; ++ni) MMA_TF32(acc[mi][ni], af[mi], bf[ni]);
        }
        __syncthreads();
    }
#pragma unroll
    for (int mi = 0; mi < 4; ++mi) {
        int r = m0 + moff + 16 * mi + grp;
#pragma unroll
        for (int ni = 0; ni < 4; ++ni) {
            int c = n0 + noff + 8 * ni + 2 * tig;
            *(float2*)&C[(size_t)r * ldc + c] = make_float2(acc[mi][ni][0], acc[mi][ni][1]);
            *(float2*)&C[(size_t)(r + 8) * ldc + c] = make_float2(acc[mi][ni][2], acc[mi][ni][3]);
        }
    }
}

// ---------------- rel logits (NT), band-restricted, pipelined ----------------
__global__ void __launch_bounds__(256, 2) rel_tc(const float* __restrict__ qrb,
                                                 const float* __restrict__ krb) {
    __shared__ float As[2][128][36];
    __shared__ float Bs[2][128][36];
    __shared__ float rbs[128];
    int z = blockIdx.z;
    int side = z >> 6, bh = z & 63, b = bh >> 5, h = bh & 31;
    const float* A = (side ? g_k : g_q) + (size_t)b * Ss * HC + h * Cc;
    const float* rb = (side ? krb : qrb) + h * Cc;
    const float* Bp = g_pos + h * Cc;
    float* Cp = (side ? g_rk : g_rq) + (size_t)bh * (Ss * P2);
    int my = blockIdx.y;
    int m0 = my * 128;
    int n0 = (blockIdx.x + 3 - my) * 128;   // band restriction: only needed p tiles
    int t = threadIdx.x, lane = t & 31, wid = t >> 5;
    int grp = lane >> 2, tig = lane & 3;
    int moff = (wid >> 2) * 64, noff = (wid & 3) * 32;
    if (t < 128) rbs[t] = rb[t];
    float acc[4][4][4] = {};
    // prologue
    {
#pragma unroll
        for (int i = 0; i < 4; ++i) {
            int idx = t + 256 * i;
            int r = idx >> 3, c4 = (idx & 7) * 4;
            cpa16(&As[0][r][c4], &A[(size_t)(m0 + r) * HC + c4]);
            cpa16(&Bs[0][r][c4], &Bp[(size_t)(n0 + r) * HC + c4]);
        }
        CPCOMMIT();
    }
    for (int ib = 0; ib < 4; ++ib) {
        CPWAIT0();
        __syncthreads();
        if (ib < 3) {
            int kb = (ib + 1) * 32;
            int st = (ib + 1) & 1;
#pragma unroll
            for (int i = 0; i < 4; ++i) {
                int idx = t + 256 * i;
                int r = idx >> 3, c4 = (idx & 7) * 4;
                cpa16(&As[st][r][c4], &A[(size_t)(m0 + r) * HC + kb + c4]);
                cpa16(&Bs[st][r][c4], &Bp[(size_t)(n0 + r) * HC + kb + c4]);
            }
            CPCOMMIT();
        }
        int st = ib & 1;
        int kbase = ib * 32;
#pragma unroll
        for (int ks = 0; ks < 4; ++ks) {
            int kk = ks * 8;
            float b0 = rbs[kbase + kk + tig], b1 = rbs[kbase + kk + tig + 4];
            uint32_t af[4][4], bf[4][2];
#pragma unroll
            for (int mi = 0; mi < 4; ++mi) {
                int r = moff + 16 * mi + grp;
                af[mi][0] = f2tf(As[st][r][kk + tig] + b0);
                af[mi][1] = f2tf(As[st][r + 8][kk + tig] + b0);
                af[mi][2] = f2tf(As[st][r][kk + tig + 4] + b1);
                af[mi][3] = f2tf(As[st][r + 8][kk + tig + 4] + b1);
            }
#pragma unroll
            for (int ni = 0; ni < 4; ++ni) {
                int c = noff + 8 * ni + grp;
                bf[ni][0] = f2tf(Bs[st][c][kk + tig]);
                bf[ni][1] = f2tf(Bs[st][c][kk + tig + 4]);
            }
#pragma unroll
            for (int mi = 0; mi < 4; ++mi)
#pragma unroll
                for (int ni = 0; ni < 4; ++ni) MMA_TF32(acc[mi][ni], af[mi], bf[ni]);
        }
        __syncthreads();
    }
#pragma unroll
    for (int mi = 0; mi < 4; ++mi) {
        int r = m0 + moff + 16 * mi + grp;
#pragma unroll
        for (int ni = 0; ni < 4; ++ni) {
            int c = n0 + noff + 8 * ni + 2 * tig;
            *(float2*)&Cp[(size_t)r * P2 + c] = make_float2(acc[mi][ni][0], acc[mi][ni][1]);
            *(float2*)&Cp[(size_t)(r + 8) * P2 + c] = make_float2(acc[mi][ni][2], acc[mi][ni][3]);
        }
    }
}

// ---------------- a = QK^T + 0.5*(rq + rk gathers) (NT), pipelined ----------------
__global__ void __launch_bounds__(256, 2) a_tc() {
    __shared__ float As[2][128][36];
    __shared__ float Bs[2][128][36];
    int bh = blockIdx.z, b = bh >> 5, h = bh & 31;
    const float* A  = g_q + (size_t)b * Ss * HC + h * Cc;
    const float* Bp = g_k + (size_t)b * Ss * HC + h * Cc;
    const float* rqb = g_rq + (size_t)bh * (Ss * P2);
    const float* rkb = g_rk + (size_t)bh * (Ss * P2);
    float* Cp = g_a + (size_t)bh * (Ss * Ss);
    int m0 = blockIdx.y * 128, n0 = blockIdx.x * 128;
    int t = threadIdx.x, lane = t & 31, wid = t >> 5;
    int grp = lane >> 2, tig = lane & 3;
    int moff = (wid >> 2) * 64, noff = (wid & 3) * 32;
    float acc[4][4][4] = {};
    {
#pragma unroll
        for (int i = 0; i < 4; ++i) {
            int idx = t + 256 * i;
            int r = idx >> 3, c4 = (idx & 7) * 4;
            cpa16(&As[0][r][c4], &A[(size_t)(m0 + r) * HC + c4]);
            cpa16(&Bs[0][r][c4], &Bp[(size_t)(n0 + r) * HC + c4]);
        }
        CPCOMMIT();
    }
    for (int ib = 0; ib < 4; ++ib) {
        CPWAIT0();
        __syncthreads();
        if (ib < 3) {
            int kb = (ib + 1) * 32;
            int st = (ib + 1) & 1;
#pragma unroll
            for (int i = 0; i < 4; ++i) {
                int idx = t + 256 * i;
                int r = idx >> 3, c4 = (idx & 7) * 4;
                cpa16(&As[st][r][c4], &A[(size_t)(m0 + r) * HC + kb + c4]);
                cpa16(&Bs[st][r][c4], &Bp[(size_t)(n0 + r) * HC + kb + c4]);
            }
            CPCOMMIT();
        }
        int st = ib & 1;
#pragma unroll
        for (int ks = 0; ks < 4; ++ks) {
            int kk = ks * 8;
            uint32_t af[4][4], bf[4][2];
#pragma unroll
            for (int mi = 0; mi < 4; ++mi) {
                int r = moff + 16 * mi + grp;
                af[mi][0] = f2tf(As[st][r][kk + tig]);
                af[mi][1] = f2tf(As[st][r + 8][kk + tig]);
                af[mi][2] = f2tf(As[st][r][kk + tig + 4]);
                af[mi][3] = f2tf(As[st][r + 8][kk + tig + 4]);
            }
#pragma unroll
            for (int ni = 0; ni < 4; ++ni) {
                int c = noff + 8 * ni + grp;
                bf[ni][0] = f2tf(Bs[st][c][kk + tig]);
                bf[ni][1] = f2tf(Bs[st][c][kk + tig + 4]);
            }
#pragma unroll
            for (int mi = 0; mi < 4; ++mi)
#pragma unroll
                for (int ni = 0; ni < 4; ++ni) MMA_TF32(acc[mi][ni], af[mi], bf[ni]);
        }
        __syncthreads();
    }
#pragma unroll
    for (int mi = 0; mi < 4; ++mi) {
        int q0 = m0 + moff + 16 * mi + grp;
#pragma unroll
        for (int ni = 0; ni < 4; ++ni) {
            int kg = n0 + noff + 8 * ni + 2 * tig;
            float rq00 = rqb[(size_t)q0 * P2 + kg - q0 + 512];
            float rq01 = rqb[(size_t)q0 * P2 + kg + 1 - q0 + 512];
            float rq10 = rqb[(size_t)(q0 + 8) * P2 + kg - q0 - 8 + 512];
            float rq11 = rqb[(size_t)(q0 + 8) * P2 + kg + 1 - q0 - 8 + 512];
            float rk00 = rkb[(size_t)kg * P2 + q0 - kg + 512];
            float rk01 = rkb[(size_t)(kg + 1) * P2 + q0 - kg - 1 + 512];
            float rk10 = rkb[(size_t)kg * P2 + q0 + 8 - kg + 512];
            float rk11 = rkb[(size_t)(kg + 1) * P2 + q0 + 7 - kg + 512];
            float2 o0 = make_float2(acc[mi][ni][0] + 0.5f * (rq00 + rk00),
                                    acc[mi][ni][1] + 0.5f * (rq01 + rk01));
            float2 o1 = make_float2(acc[mi][ni][2] + 0.5f * (rq10 + rk10),
                                    acc[mi][ni][3] + 0.5f * (rq11 + rk11));
            *(float2*)&Cp[(size_t)q0 * Ss + kg] = o0;
            *(float2*)&Cp[(size_t)(q0 + 8) * Ss + kg] = o1;
        }
    }
}

// ---------------- final: out = a(h) @ w_pair + b_pair + yq + yk ----------------
__global__ void __launch_bounds__(256) final_tc(const float* __restrict__ wpair,
                                                const float* __restrict__ bpair,
                                                float* __restrict__ out) {
    __shared__ uint32_t At[32][136];
    __shared__ uint32_t Ws[32][136];
    __shared__ float basef[128];
    int k0 = blockIdx.x * 128, q = blockIdx.y, b = blockIdx.z;
    int t = threadIdx.x, lane = t & 31, wid = t >> 5;
    int grp = lane >> 2, tig = lane & 3;
    int moff = (wid >> 2) * 64, noff = (wid & 3) * 32;
#pragma unroll
    for (int i = 0; i < 4; ++i) {
        int idx = t + 256 * i;
        int r = idx >> 5, c4 = (idx & 31) * 4;
        float4 w = *(const float4*)&wpair[r * 128 + c4];
        Ws[r][c4] = f2tf(w.x); Ws[r][c4 + 1] = f2tf(w.y);
        Ws[r][c4 + 2] = f2tf(w.z); Ws[r][c4 + 3] = f2tf(w.w);
        float4 v = *(const float4*)&g_a[(((size_t)(b * 32 + r) * Ss + q) * Ss) + k0 + c4];
        At[r][c4] = f2tf(v.x); At[r][c4 + 1] = f2tf(v.y);
        At[r][c4 + 2] = f2tf(v.z); At[r][c4 + 3] = f2tf(v.w);
    }
    if (t < 128) basef[t] = bpair[t] + g_yq[(size_t)(b * 512 + q) * 128 + t];
    __syncthreads();
    float acc[4][4][4] = {};
#pragma unroll
    for (int ks = 0; ks < 4; ++ks) {
        int kk = ks * 8;
        uint32_t af[4][4], bf[4][2];
#pragma unroll
        for (int mi = 0; mi < 4; ++mi) {
            int r = moff + 16 * mi + grp;
            af[mi][0] = At[kk + tig][r];     af[mi][1] = At[kk + tig][r + 8];
            af[mi][2] = At[kk + tig + 4][r]; af[mi][3] = At[kk + tig + 4][r + 8];
        }
#pragma unroll
        for (int ni = 0; ni < 4; ++ni) {
            int c = noff + 8 * ni + grp;
            bf[ni][0] = Ws[kk + tig][c]; bf[ni][1] = Ws[kk + tig + 4][c];
        }
#pragma unroll
        for (int mi = 0; mi < 4; ++mi)
#pragma unroll
            for (int ni = 0; ni < 4; ++ni) MMA_TF32(acc[mi][ni], af[mi], bf[ni]);
    }
#pragma unroll
    for (int mi = 0; mi < 4; ++mi) {
        int kl0 = moff + 16 * mi + grp;
        size_t row0 = ((size_t)(b * 512 + q) * 512 + k0 + kl0) * 128;
        size_t row1 = row0 + (size_t)8 * 128;
        const float* yk0 = &g_yk[(size_t)(b * 512 + k0 + kl0) * 128];
        const float* yk1 = yk0 + 8 * 128;
#pragma unroll
        for (int ni = 0; ni < 4; ++ni) {
            int f = noff + 8 * ni + 2 * tig;
            float2 y0 = *(const float2*)&yk0[f];
            float2 y1 = *(const float2*)&yk1[f];
            float2 o0 = make_float2(acc[mi][ni][0] + basef[f] + y0.x,
                                    acc[mi][ni][1] + basef[f + 1] + y0.y);
            float2 o1 = make_float2(acc[mi][ni][2] + basef[f] + y1.x,
                                    acc[mi][ni][3] + basef[f + 1] + y1.y);
            *(float2*)&out[row0 + f] = o0;
            *(float2*)&out[row1 + f] = o1;
        }
    }
}

// ---------------- launcher ----------------
extern "C" void kernel_launch(void* const* d_in, const int* in_sizes, int n_in,
                              void* d_out, int out_size) {
    const float* x        = (const float*)d_in[0];
    const float* scale    = (const float*)d_in[1];
    const float* w_q      = (const float*)d_in[2];
    const float* w_k      = (const float*)d_in[3];
    const float* w_pos    = (const float*)d_in[4];
    const float* b_pos    = (const float*)d_in[5];
    const float* q_r_bias = (const float*)d_in[6];
    const float* k_r_bias = (const float*)d_in[7];
    const float* w_yq     = (const float*)d_in[8];
    const float* w_yk     = (const float*)d_in[9];
    const float* w_pair   = (const float*)d_in[10];
    const float* b_pair   = (const float*)d_in[11];
    float* out = (float*)d_out;

    float *p_xp, *p_g, *p_q, *p_k, *p_ypart;
    cudaGetSymbolAddress((void**)&p_xp, g_xp);
    cudaGetSymbolAddress((void**)&p_g, g_g);
    cudaGetSymbolAddress((void**)&p_q, g_q);
    cudaGetSymbolAddress((void**)&p_k, g_k);
    cudaGetSymbolAddress((void**)&p_ypart, g_ypart);

    init_cw_kernel<<<1, 32>>>();
    fmin_kernel<<<5, 128>>>();
    pool_norm_kernel<<<1024, 384>>>(x, scale);
    suffix_kernel<<<16, 256>>>(w_pos);
    posenc_kernel<<<dim3(1024, 4), 256>>>(b_pos);
    // q, k projections: M=1024, N=4096, K=1536
    gemm_nn_tc<<<dim3(32, 8, 1), 256>>>(p_xp, w_q, p_q, Dd, HC, HC, Dd, 0);
    gemm_nn_tc<<<dim3(32, 8, 1), 256>>>(p_xp, w_k, p_k, Dd, HC, HC, Dd, 0);
    // y projections via k-split (8 slices of 192)
    gemm_nn_tc<<<dim3(1, 8, 8), 256>>>(p_g, w_yq, p_ypart, Dd, PAIRF, PAIRF, 192, 131072LL);
    gemm_nn_tc<<<dim3(1, 8, 8), 256>>>(p_g, w_yk, p_ypart + 8 * 131072, Dd, PAIRF, PAIRF, 192, 131072LL);
    reduce_y_kernel<<<512, 256>>>();
    // rel logits: band-restricted (5 of 8 p-tiles per q-tile)
    rel_tc<<<dim3(5, 4, 128), 256>>>(q_r_bias, k_r_bias);
    // a = QK^T + 0.5*(rq+rk)
    a_tc<<<dim3(4, 4, 64), 256>>>();
    // head->pair projection + biases + y terms
    final_tc<<<dim3(4, 512, 2), 256>>>(w_pair, b_pair, out);
}

// round 5
// speedup vs baseline: 3.8502x; 1.2797x over previous
#include <cuda_runtime.h>
#include <cuda_fp16.h>
#include <math.h>
#include <stdint.h>

#define Bb 2
#define Dd 1536
#define Ss 512
#define Hh 32
#define Cc 128
#define HC 4096
#define Ff 32
#define PAIRF 128
#define P2 1024

// ---------------- scratch (device globals) ----------------
__device__ __half g_xph[Bb*Ss*Dd];
__device__ __half g_gh [Bb*Ss*Dd];
__device__ __half g_qh [Bb*Ss*HC];
__device__ __half g_kh [Bb*Ss*HC];
__device__ __half g_qbh[Bb*Ss*HC];     // q + q_r_bias
__device__ __half g_kbh[Bb*Ss*HC];     // k + k_r_bias
__device__ __half g_posh[P2*HC];
__device__ __half g_wqt[HC*Dd];        // w_q^T  [4096][1536]
__device__ __half g_wkt[HC*Dd];
__device__ __half g_wyqt[PAIRF*Dd];    // [128][1536]
__device__ __half g_wykt[PAIRF*Dd];
__device__ __half g_wpt[PAIRF*Hh];     // w_pair^T [128][32]
__device__ __half g_ah[(size_t)Bb*Hh*Ss*Ss];
__device__ float g_sufq[Ff*HC];
__device__ float g_sufs[Ff*HC];
__device__ float g_cw[Ff];
__device__ int   g_fmin[513];
__device__ float g_yq[Bb*Ss*PAIRF];
__device__ float g_yk[Bb*Ss*PAIRF];
__device__ float g_ypart[16*Bb*Ss*PAIRF];
__device__ float g_rq[(size_t)Bb*Hh*Ss*P2];
__device__ float g_rk[(size_t)Bb*Hh*Ss*P2];

// ---------------- helpers ----------------
__device__ __forceinline__ __half2 h2(float a, float b) {
    return __halves2half2(__float2half_rn(a), __float2half_rn(b));
}

#define MMA_F16(d, a, b) asm volatile( \
    "mma.sync.aligned.m16n8k16.row.col.f32.f16.f16.f32 " \
    "{%0,%1,%2,%3}, {%4,%5,%6,%7}, {%8,%9}, {%0,%1,%2,%3};\n" \
    : "+f"((d)[0]), "+f"((d)[1]), "+f"((d)[2]), "+f"((d)[3]) \
    : "r"((a)[0]), "r"((a)[1]), "r"((a)[2]), "r"((a)[3]), \
      "r"((b)[0]), "r"((b)[1]))

__device__ __forceinline__ void cpa16(void* dst, const void* src) {
    uint32_t d = (uint32_t)__cvta_generic_to_shared(dst);
    asm volatile("cp.async.ca.shared.global [%0], [%1], 16;\n" :: "r"(d), "l"(src));
}
#define CPCOMMIT() asm volatile("cp.async.commit_group;\n")
#define CPWAIT0()  asm volatile("cp.async.wait_group 0;\n")

// stage a 128-row x 32-half tile into smem [128][40]
__device__ __forceinline__ void cp_tile(__half (*dst)[40], const __half* src, int ld, int t) {
#pragma unroll
    for (int i = 0; i < 2; ++i) {
        int c = t + 256 * i;
        int r = c >> 2, c16 = (c & 3) * 8;
        cpa16(&dst[r][c16], src + (size_t)r * ld + c16);
    }
}

// fragment compute for one 32-K stage (2 k-steps of 16)
#define STAGE_MMA(As_, Bs_)                                                    \
    _Pragma("unroll")                                                          \
    for (int ks = 0; ks < 2; ++ks) {                                           \
        int koff = ks * 16 + 2 * tig;                                          \
        uint32_t af[4][4], bf[4][2];                                           \
        _Pragma("unroll")                                                      \
        for (int mi = 0; mi < 4; ++mi) {                                       \
            int r = moff + 16 * mi + grp;                                      \
            af[mi][0] = *(const uint32_t*)&As_[r][koff];                       \
            af[mi][1] = *(const uint32_t*)&As_[r + 8][koff];                   \
            af[mi][2] = *(const uint32_t*)&As_[r][koff + 8];                   \
            af[mi][3] = *(const uint32_t*)&As_[r + 8][koff + 8];               \
        }                                                                      \
        _Pragma("unroll")                                                      \
        for (int ni = 0; ni < 4; ++ni) {                                       \
            int c = noff + 8 * ni + grp;                                       \
            bf[ni][0] = *(const uint32_t*)&Bs_[c][koff];                       \
            bf[ni][1] = *(const uint32_t*)&Bs_[c][koff + 8];                   \
        }                                                                      \
        _Pragma("unroll")                                                      \
        for (int mi = 0; mi < 4; ++mi)                                         \
            _Pragma("unroll")                                                  \
            for (int ni = 0; ni < 4; ++ni) MMA_F16(acc[mi][ni], af[mi], bf[ni]); \
    }

// ---------------- small init kernels ----------------
__global__ void init_cw_kernel() {
    int f = threadIdx.x;
    if (f < Ff)
        g_cw[f] = (float)((double)f + exp(log(481.0) * ((double)f / 32.0)));
}

__global__ void fmin_kernel() {
    int d = blockIdx.x * 128 + threadIdx.x;
    if (d <= 512) {
        int fm = 32;
        for (int f = 31; f >= 0; --f)
            if (g_cw[f] > (float)d) fm = f;
        g_fmin[d] = fm;
    }
}

// fp32 [K][N] -> half [N][K]
__global__ void transpose_h(const float* __restrict__ src, __half* __restrict__ dst,
                            int K, int N) {
    __shared__ float s[32][33];
    int n0 = blockIdx.x * 32, k0 = blockIdx.y * 32;
    int tx = threadIdx.x, ty = threadIdx.y;
#pragma unroll
    for (int i = 0; i < 4; ++i)
        s[ty + 8 * i][tx] = src[(size_t)(k0 + ty + 8 * i) * N + n0 + tx];
    __syncthreads();
#pragma unroll
    for (int i = 0; i < 4; ++i)
        dst[(size_t)(n0 + ty + 8 * i) * K + k0 + tx] = __float2half_rn(s[tx][ty + 8 * i]);
}

// pool(16) + RMSNorm + gelu -> half scratch
__global__ void __launch_bounds__(384) pool_norm_kernel(const float* __restrict__ x,
                                                        const float* __restrict__ scale) {
    int row = blockIdx.x;
    int t = threadIdx.x;
    const float* xr = x + (size_t)row * 16 * Dd;
    float pooled[4];
    float ss = 0.f;
#pragma unroll
    for (int u = 0; u < 4; ++u) {
        int d = t + u * 384;
        float s = 0.f;
#pragma unroll
        for (int j = 0; j < 16; ++j) s += xr[(size_t)j * Dd + d];
        s *= 0.0625f;
        pooled[u] = s;
        ss += s * s;
    }
    __shared__ float red[13];
#pragma unroll
    for (int o = 16; o; o >>= 1) ss += __shfl_xor_sync(0xffffffffu, ss, o);
    if ((t & 31) == 0) red[t >> 5] = ss;
    __syncthreads();
    if (t == 0) {
        float tot = 0.f;
        for (int i = 0; i < 12; ++i) tot += red[i];
        red[12] = rsqrtf(tot * (1.f / 1536.f) + 1e-5f);
    }
    __syncthreads();
    float inv = red[12];
#pragma unroll
    for (int u = 0; u < 4; ++u) {
        int d = t + u * 384;
        float v = pooled[u] * inv * scale[d];
        g_xph[(size_t)row * Dd + d] = __float2half_rn(v);
        float v3 = v * v * v;
        float gl = 0.5f * v * (1.f + tanhf(0.7978845608028654f * (v + 0.044715f * v3)));
        g_gh[(size_t)row * Dd + d] = __float2half_rn(gl);
    }
}

__global__ void suffix_kernel(const float* __restrict__ wpos) {
    int hc = blockIdx.x * 256 + threadIdx.x;
    float aq = 0.f, as = 0.f;
    for (int f = Ff - 1; f >= 0; --f) {
        aq += wpos[f * HC + hc];
        as += wpos[(Ff + f) * HC + hc];
        g_sufq[f * HC + hc] = aq;
        g_sufs[f * HC + hc] = as;
    }
}

__global__ void __launch_bounds__(256) posenc_kernel(const float* __restrict__ bpos) {
    int p = blockIdx.x;
    int hc4 = (blockIdx.y * 256 + threadIdx.x) * 4;
    int dist = (p >= 512) ? p - 512 : 512 - p;
    int fm = g_fmin[dist];
    float4 v = *(const float4*)&bpos[hc4];
    if (fm < 32) {
        float sg = (p > 512) ? 1.f : ((p < 512) ? -1.f : 0.f);
        float4 a = *(const float4*)&g_sufq[fm * HC + hc4];
        float4 s = *(const float4*)&g_sufs[fm * HC + hc4];
        v.x += a.x + sg * s.x; v.y += a.y + sg * s.y;
        v.z += a.z + sg * s.z; v.w += a.w + sg * s.w;
    }
    __half2* dst = (__half2*)&g_posh[(size_t)p * HC + hc4];
    dst[0] = h2(v.x, v.y);
    dst[1] = h2(v.z, v.w);
}

__global__ void reduce_y_kernel() {
    int i = blockIdx.x * 256 + threadIdx.x;
    float sq = 0.f, sk = 0.f;
#pragma unroll
    for (int s = 0; s < 8; ++s) {
        sq += g_ypart[s * 131072 + i];
        sk += g_ypart[(8 + s) * 131072 + i];
    }
    g_yq[i] = sq;
    g_yk[i] = sk;
}

// ---------------- q/k projections: C = xp @ W^T (NT, fp16 mma) ----------------
__global__ void __launch_bounds__(256, 2) proj_tc(const float* __restrict__ qrb,
                                                  const float* __restrict__ krb) {
    __shared__ __half As[2][128][40];
    __shared__ __half Bs[2][128][40];
    int sel = blockIdx.z;
    const __half* A  = g_xph;
    const __half* Bt = sel ? g_wkt : g_wqt;
    __half* Oq = sel ? g_kh : g_qh;
    __half* Ob = sel ? g_kbh : g_qbh;
    const float* bias = sel ? krb : qrb;
    int m0 = blockIdx.y * 128, n0 = blockIdx.x * 128;
    int t = threadIdx.x, lane = t & 31, wid = t >> 5;
    int grp = lane >> 2, tig = lane & 3;
    int moff = (wid >> 2) * 64, noff = (wid & 3) * 32;
    float acc[4][4][4] = {};
    const __half* Ab = A + (size_t)m0 * Dd;
    const __half* Bp = Bt + (size_t)n0 * Dd;
    cp_tile(As[0], Ab, Dd, t);
    cp_tile(Bs[0], Bp, Dd, t);
    CPCOMMIT();
    for (int ib = 0; ib < 48; ++ib) {
        CPWAIT0();
        __syncthreads();
        if (ib < 47) {
            int st = (ib + 1) & 1, kb = (ib + 1) * 32;
            cp_tile(As[st], Ab + kb, Dd, t);
            cp_tile(Bs[st], Bp + kb, Dd, t);
            CPCOMMIT();
        }
        int st = ib & 1;
        STAGE_MMA(As[st], Bs[st]);
        __syncthreads();
    }
#pragma unroll
    for (int mi = 0; mi < 4; ++mi) {
        int r = m0 + moff + 16 * mi + grp;
#pragma unroll
        for (int ni = 0; ni < 4; ++ni) {
            int c = n0 + noff + 8 * ni + 2 * tig;
            float2 bv = *(const float2*)&bias[c];
            size_t o0 = (size_t)r * HC + c, o1 = (size_t)(r + 8) * HC + c;
            *(__half2*)&Oq[o0] = h2(acc[mi][ni][0], acc[mi][ni][1]);
            *(__half2*)&Oq[o1] = h2(acc[mi][ni][2], acc[mi][ni][3]);
            *(__half2*)&Ob[o0] = h2(acc[mi][ni][0] + bv.x, acc[mi][ni][1] + bv.y);
            *(__half2*)&Ob[o1] = h2(acc[mi][ni][2] + bv.x, acc[mi][ni][3] + bv.y);
        }
    }
}

// ---------------- y projections (k-split, NT fp16) ----------------
__global__ void __launch_bounds__(256, 2) ygemm_tc() {
    __shared__ __half As[2][128][40];
    __shared__ __half Bs[2][128][40];
    int z = blockIdx.z;
    int side = z >> 3, slice = z & 7;
    const __half* Bt = side ? g_wykt : g_wyqt;
    int m0 = blockIdx.y * 128;
    int kstart = slice * 192;
    int t = threadIdx.x, lane = t & 31, wid = t >> 5;
    int grp = lane >> 2, tig = lane & 3;
    int moff = (wid >> 2) * 64, noff = (wid & 3) * 32;
    float acc[4][4][4] = {};
    const __half* Ab = g_gh + (size_t)m0 * Dd + kstart;
    const __half* Bp = Bt + kstart;
    cp_tile(As[0], Ab, Dd, t);
    cp_tile(Bs[0], Bp, Dd, t);
    CPCOMMIT();
    for (int ib = 0; ib < 6; ++ib) {
        CPWAIT0();
        __syncthreads();
        if (ib < 5) {
            int st = (ib + 1) & 1, kb = (ib + 1) * 32;
            cp_tile(As[st], Ab + kb, Dd, t);
            cp_tile(Bs[st], Bp + kb, Dd, t);
            CPCOMMIT();
        }
        int st = ib & 1;
        STAGE_MMA(As[st], Bs[st]);
        __syncthreads();
    }
    float* Cp = g_ypart + (size_t)z * 131072;
#pragma unroll
    for (int mi = 0; mi < 4; ++mi) {
        int r = m0 + moff + 16 * mi + grp;
#pragma unroll
        for (int ni = 0; ni < 4; ++ni) {
            int c = noff + 8 * ni + 2 * tig;
            *(float2*)&Cp[(size_t)r * 128 + c] = make_float2(acc[mi][ni][0], acc[mi][ni][1]);
            *(float2*)&Cp[(size_t)(r + 8) * 128 + c] = make_float2(acc[mi][ni][2], acc[mi][ni][3]);
        }
    }
}

// ---------------- rel logits (NT, band-restricted, fp16) ----------------
__global__ void __launch_bounds__(256, 2) rel_tc() {
    __shared__ __half As[2][128][40];
    __shared__ __half Bs[2][128][40];
    int z = blockIdx.z;
    int side = z >> 6, bh = z & 63, b = bh >> 5, h = bh & 31;
    const __half* A  = (side ? g_kbh : g_qbh) + (size_t)b * Ss * HC + h * Cc;
    const __half* Bt = g_posh + h * Cc;
    float* Cp = (side ? g_rk : g_rq) + (size_t)bh * (Ss * P2);
    int my = blockIdx.y;
    int m0 = my * 128;
    int n0 = (blockIdx.x + 3 - my) * 128;
    int t = threadIdx.x, lane = t & 31, wid = t >> 5;
    int grp = lane >> 2, tig = lane & 3;
    int moff = (wid >> 2) * 64, noff = (wid & 3) * 32;
    float acc[4][4][4] = {};
    const __half* Ab = A + (size_t)m0 * HC;
    const __half* Bp = Bt + (size_t)n0 * HC;
    cp_tile(As[0], Ab, HC, t);
    cp_tile(Bs[0], Bp, HC, t);
    CPCOMMIT();
    for (int ib = 0; ib < 4; ++ib) {
        CPWAIT0();
        __syncthreads();
        if (ib < 3) {
            int st = (ib + 1) & 1, kb = (ib + 1) * 32;
            cp_tile(As[st], Ab + kb, HC, t);
            cp_tile(Bs[st], Bp + kb, HC, t);
            CPCOMMIT();
        }
        int st = ib & 1;
        STAGE_MMA(As[st], Bs[st]);
        __syncthreads();
    }
#pragma unroll
    for (int mi = 0; mi < 4; ++mi) {
        int r = m0 + moff + 16 * mi + grp;
#pragma unroll
        for (int ni = 0; ni < 4; ++ni) {
            int c = n0 + noff + 8 * ni + 2 * tig;
            *(float2*)&Cp[(size_t)r * P2 + c] = make_float2(acc[mi][ni][0], acc[mi][ni][1]);
            *(float2*)&Cp[(size_t)(r + 8) * P2 + c] = make_float2(acc[mi][ni][2], acc[mi][ni][3]);
        }
    }
}

// ---------------- a = QK^T + 0.5*(rq + rk gathers), writes half ----------------
__global__ void __launch_bounds__(256, 2) a_tc() {
    __shared__ __half As[2][128][40];
    __shared__ __half Bs[2][128][40];
    int bh = blockIdx.z, b = bh >> 5, h = bh & 31;
    const __half* A  = g_qh + (size_t)b * Ss * HC + h * Cc;
    const __half* Bt = g_kh + (size_t)b * Ss * HC + h * Cc;
    const float* rqb = g_rq + (size_t)bh * (Ss * P2);
    const float* rkb = g_rk + (size_t)bh * (Ss * P2);
    __half* Cp = g_ah + (size_t)bh * (Ss * Ss);
    int m0 = blockIdx.y * 128, n0 = blockIdx.x * 128;
    int t = threadIdx.x, lane = t & 31, wid = t >> 5;
    int grp = lane >> 2, tig = lane & 3;
    int moff = (wid >> 2) * 64, noff = (wid & 3) * 32;
    float acc[4][4][4] = {};
    const __half* Ab = A + (size_t)m0 * HC;
    const __half* Bp = Bt + (size_t)n0 * HC;
    cp_tile(As[0], Ab, HC, t);
    cp_tile(Bs[0], Bp, HC, t);
    CPCOMMIT();
    for (int ib = 0; ib < 4; ++ib) {
        CPWAIT0();
        __syncthreads();
        if (ib < 3) {
            int st = (ib + 1) & 1, kb = (ib + 1) * 32;
            cp_tile(As[st], Ab + kb, HC, t);
            cp_tile(Bs[st], Bp + kb, HC, t);
            CPCOMMIT();
        }
        int st = ib & 1;
        STAGE_MMA(As[st], Bs[st]);
        __syncthreads();
    }
#pragma unroll
    for (int mi = 0; mi < 4; ++mi) {
        int q0 = m0 + moff + 16 * mi + grp;
#pragma unroll
        for (int ni = 0; ni < 4; ++ni) {
            int kg = n0 + noff + 8 * ni + 2 * tig;
            float rq00 = rqb[(size_t)q0 * P2 + kg - q0 + 512];
            float rq01 = rqb[(size_t)q0 * P2 + kg + 1 - q0 + 512];
            float rq10 = rqb[(size_t)(q0 + 8) * P2 + kg - q0 - 8 + 512];
            float rq11 = rqb[(size_t)(q0 + 8) * P2 + kg + 1 - q0 - 8 + 512];
            float rk00 = rkb[(size_t)kg * P2 + q0 - kg + 512];
            float rk01 = rkb[(size_t)(kg + 1) * P2 + q0 - kg - 1 + 512];
            float rk10 = rkb[(size_t)kg * P2 + q0 + 8 - kg + 512];
            float rk11 = rkb[(size_t)(kg + 1) * P2 + q0 + 7 - kg + 512];
            *(__half2*)&Cp[(size_t)q0 * Ss + kg] =
                h2(acc[mi][ni][0] + 0.5f * (rq00 + rk00),
                   acc[mi][ni][1] + 0.5f * (rq01 + rk01));
            *(__half2*)&Cp[(size_t)(q0 + 8) * Ss + kg] =
                h2(acc[mi][ni][2] + 0.5f * (rq10 + rk10),
                   acc[mi][ni][3] + 0.5f * (rq11 + rk11));
        }
    }
}

// ---------------- final: out = a(h) @ w_pair + b_pair + yq + yk ----------------
__global__ void __launch_bounds__(256) final_tc(const float* __restrict__ bpair,
                                                float* __restrict__ out) {
    __shared__ __half At_s[128][34];   // [k_local][h]
    __shared__ __half Ws[128][40];     // [f][h]
    __shared__ float basef[128];
    int k0 = blockIdx.x * 128, q = blockIdx.y, b = blockIdx.z;
    int t = threadIdx.x, lane = t & 31, wid = t >> 5;
    int grp = lane >> 2, tig = lane & 3;
    int moff = (wid >> 2) * 64, noff = (wid & 3) * 32;
    cp_tile(Ws, g_wpt, 32, t);
    CPCOMMIT();
#pragma unroll
    for (int it = 0; it < 8; ++it) {
        int id = t + 256 * it;        // 2048 half2
        int hh = id >> 6, j = id & 63;
        __half2 v = *(const __half2*)&g_ah[(((size_t)(b * 32 + hh) * Ss + q) * Ss) + k0 + 2 * j];
        At_s[2 * j][hh] = __low2half(v);
        At_s[2 * j + 1][hh] = __high2half(v);
    }
    if (t < 128) basef[t] = bpair[t] + g_yq[(size_t)(b * 512 + q) * 128 + t];
    CPWAIT0();
    __syncthreads();
    float acc[4][4][4] = {};
#pragma unroll
    for (int ks = 0; ks < 2; ++ks) {
        int koff = ks * 16 + 2 * tig;
        uint32_t af[4][4], bf[4][2];
#pragma unroll
        for (int mi = 0; mi < 4; ++mi) {
            int r = moff + 16 * mi + grp;
            af[mi][0] = *(const uint32_t*)&At_s[r][koff];
            af[mi][1] = *(const uint32_t*)&At_s[r + 8][koff];
            af[mi][2] = *(const uint32_t*)&At_s[r][koff + 8];
            af[mi][3] = *(const uint32_t*)&At_s[r + 8][koff + 8];
        }
#pragma unroll
        for (int ni = 0; ni < 4; ++ni) {
            int c = noff + 8 * ni + grp;
            bf[ni][0] = *(const uint32_t*)&Ws[c][koff];
            bf[ni][1] = *(const uint32_t*)&Ws[c][koff + 8];
        }
#pragma unroll
        for (int mi = 0; mi < 4; ++mi)
#pragma unroll
            for (int ni = 0; ni < 4; ++ni) MMA_F16(acc[mi][ni], af[mi], bf[ni]);
    }
#pragma unroll
    for (int mi = 0; mi < 4; ++mi) {
        int kl0 = moff + 16 * mi + grp;
        size_t row0 = ((size_t)(b * 512 + q) * 512 + k0 + kl0) * 128;
        size_t row1 = row0 + (size_t)8 * 128;
        const float* yk0 = &g_yk[(size_t)(b * 512 + k0 + kl0) * 128];
        const float* yk1 = yk0 + 8 * 128;
#pragma unroll
        for (int ni = 0; ni < 4; ++ni) {
            int f = noff + 8 * ni + 2 * tig;
            float2 y0 = *(const float2*)&yk0[f];
            float2 y1 = *(const float2*)&yk1[f];
            *(float2*)&out[row0 + f] = make_float2(acc[mi][ni][0] + basef[f] + y0.x,
                                                   acc[mi][ni][1] + basef[f + 1] + y0.y);
            *(float2*)&out[row1 + f] = make_float2(acc[mi][ni][2] + basef[f] + y1.x,
                                                   acc[mi][ni][3] + basef[f + 1] + y1.y);
        }
    }
}

// ---------------- launcher ----------------
extern "C" void kernel_launch(void* const* d_in, const int* in_sizes, int n_in,
                              void* d_out, int out_size) {
    const float* x        = (const float*)d_in[0];
    const float* scale    = (const float*)d_in[1];
    const float* w_q      = (const float*)d_in[2];
    const float* w_k      = (const float*)d_in[3];
    const float* w_pos    = (const float*)d_in[4];
    const float* b_pos    = (const float*)d_in[5];
    const float* q_r_bias = (const float*)d_in[6];
    const float* k_r_bias = (const float*)d_in[7];
    const float* w_yq     = (const float*)d_in[8];
    const float* w_yk     = (const float*)d_in[9];
    const float* w_pair   = (const float*)d_in[10];
    const float* b_pair   = (const float*)d_in[11];
    float* out = (float*)d_out;

    __half *p_wqt, *p_wkt, *p_wyqt, *p_wykt, *p_wpt;
    cudaGetSymbolAddress((void**)&p_wqt, g_wqt);
    cudaGetSymbolAddress((void**)&p_wkt, g_wkt);
    cudaGetSymbolAddress((void**)&p_wyqt, g_wyqt);
    cudaGetSymbolAddress((void**)&p_wykt, g_wykt);
    cudaGetSymbolAddress((void**)&p_wpt, g_wpt);

    init_cw_kernel<<<1, 32>>>();
    fmin_kernel<<<5, 128>>>();
    transpose_h<<<dim3(128, 48), dim3(32, 8)>>>(w_q, p_wqt, Dd, HC);
    transpose_h<<<dim3(128, 48), dim3(32, 8)>>>(w_k, p_wkt, Dd, HC);
    transpose_h<<<dim3(4, 48), dim3(32, 8)>>>(w_yq, p_wyqt, Dd, PAIRF);
    transpose_h<<<dim3(4, 48), dim3(32, 8)>>>(w_yk, p_wykt, Dd, PAIRF);
    transpose_h<<<dim3(4, 1), dim3(32, 8)>>>(w_pair, p_wpt, Hh, PAIRF);
    pool_norm_kernel<<<1024, 384>>>(x, scale);
    suffix_kernel<<<16, 256>>>(w_pos);
    posenc_kernel<<<dim3(1024, 4), 256>>>(b_pos);
    // q & k projections in one launch (z = 0: q, z = 1: k)
    proj_tc<<<dim3(32, 8, 2), 256>>>(q_r_bias, k_r_bias);
    // y projections, k-split (z: side*8 + slice)
    ygemm_tc<<<dim3(1, 8, 16), 256>>>();
    reduce_y_kernel<<<512, 256>>>();
    // rel logits: band-restricted
    rel_tc<<<dim3(5, 4, 128), 256>>>();
    // a = QK^T + 0.5*(rq+rk)
    a_tc<<<dim3(4, 4, 64), 256>>>();
    // head->pair projection + biases + y terms
    final_tc<<<dim3(4, 512, 2), 256>>>(b_pair, out);
}

// round 6
// speedup vs baseline: 4.1165x; 1.0692x over previous
#include <cuda_runtime.h>
#include <cuda_fp16.h>
#include <math.h>
#include <stdint.h>

#define Bb 2
#define Dd 1536
#define Ss 512
#define Hh 32
#define Cc 128
#define HC 4096
#define Ff 32
#define PAIRF 128
#define P2 1024
#define TW 72   // smem tile row width (halfs) for 64-wide K stages

// ---------------- scratch (device globals) ----------------
__device__ __half g_xph[Bb*Ss*Dd];
__device__ __half g_gh [Bb*Ss*Dd];
__device__ __half g_qh [Bb*Ss*HC];
__device__ __half g_kh [Bb*Ss*HC];
__device__ __half g_qbh[Bb*Ss*HC];
__device__ __half g_kbh[Bb*Ss*HC];
__device__ __half g_posh[P2*HC];
__device__ __half g_wqt[HC*Dd];
__device__ __half g_wkt[HC*Dd];
__device__ __half g_wyqt[PAIRF*Dd];
__device__ __half g_wykt[PAIRF*Dd];
__device__ __half g_wpt[PAIRF*Hh];
__device__ __half g_ah[(size_t)Bb*Hh*Ss*Ss];
__device__ __half g_rqh[(size_t)Bb*Hh*Ss*P2];
__device__ __half g_rkh[(size_t)Bb*Hh*Ss*P2];
__device__ float g_sufq[Ff*HC];
__device__ float g_sufs[Ff*HC];
__device__ float g_cw[Ff];
__device__ int   g_fmin[513];
__device__ float g_yq[Bb*Ss*PAIRF];
__device__ float g_yk[Bb*Ss*PAIRF];
__device__ float g_ypart[16*Bb*Ss*PAIRF];

// ---------------- helpers ----------------
__device__ __forceinline__ __half2 h2(float a, float b) {
    return __halves2half2(__float2half_rn(a), __float2half_rn(b));
}

#define MMA_F16(d, a, b) asm volatile( \
    "mma.sync.aligned.m16n8k16.row.col.f32.f16.f16.f32 " \
    "{%0,%1,%2,%3}, {%4,%5,%6,%7}, {%8,%9}, {%0,%1,%2,%3};\n" \
    : "+f"((d)[0]), "+f"((d)[1]), "+f"((d)[2]), "+f"((d)[3]) \
    : "r"((a)[0]), "r"((a)[1]), "r"((a)[2]), "r"((a)[3]), \
      "r"((b)[0]), "r"((b)[1]))

__device__ __forceinline__ void cpa16(void* dst, const void* src) {
    uint32_t d = (uint32_t)__cvta_generic_to_shared(dst);
    asm volatile("cp.async.ca.shared.global [%0], [%1], 16;\n" :: "r"(d), "l"(src));
}
#define CPCOMMIT() asm volatile("cp.async.commit_group;\n")
#define CPWAIT0()  asm volatile("cp.async.wait_group 0;\n")

typedef __half (*Tile)[TW];

// stage a 128-row x 64-half tile into smem [128][TW]
__device__ __forceinline__ void cp_tile64(Tile dst, const __half* src, int ld, int t) {
#pragma unroll
    for (int i = 0; i < 4; ++i) {
        int c = t + 256 * i;
        int r = c >> 3, c16 = (c & 7) * 8;
        cpa16(&dst[r][c16], src + (size_t)r * ld + c16);
    }
}

// fragment compute for one 64-K stage (4 k-steps of 16)
#define STAGE_MMA64(As_, Bs_)                                                  \
    _Pragma("unroll")                                                          \
    for (int ks = 0; ks < 4; ++ks) {                                           \
        int koff = ks * 16 + 2 * tig;                                          \
        uint32_t af[4][4], bf[4][2];                                           \
        _Pragma("unroll")                                                      \
        for (int mi = 0; mi < 4; ++mi) {                                       \
            int r = moff + 16 * mi + grp;                                      \
            af[mi][0] = *(const uint32_t*)&As_[r][koff];                       \
            af[mi][1] = *(const uint32_t*)&As_[r + 8][koff];                   \
            af[mi][2] = *(const uint32_t*)&As_[r][koff + 8];                   \
            af[mi][3] = *(const uint32_t*)&As_[r + 8][koff + 8];               \
        }                                                                      \
        _Pragma("unroll")                                                      \
        for (int ni = 0; ni < 4; ++ni) {                                       \
            int c = noff + 8 * ni + grp;                                       \
            bf[ni][0] = *(const uint32_t*)&Bs_[c][koff];                       \
            bf[ni][1] = *(const uint32_t*)&Bs_[c][koff + 8];                   \
        }                                                                      \
        _Pragma("unroll")                                                      \
        for (int mi = 0; mi < 4; ++mi)                                         \
            _Pragma("unroll")                                                  \
            for (int ni = 0; ni < 4; ++ni) MMA_F16(acc[mi][ni], af[mi], bf[ni]); \
    }

#define SMEMB (4 * 128 * TW * 2)   // 73728 bytes

// ---------------- small init kernels ----------------
__global__ void init_cw_kernel() {
    int f = threadIdx.x;
    if (f < Ff)
        g_cw[f] = (float)((double)f + exp(log(481.0) * ((double)f / 32.0)));
}

__global__ void fmin_kernel() {
    int d = blockIdx.x * 128 + threadIdx.x;
    if (d <= 512) {
        int fm = 32;
        for (int f = 31; f >= 0; --f)
            if (g_cw[f] > (float)d) fm = f;
        g_fmin[d] = fm;
    }
}

// fp32 [K][N] -> half [N][K]
__global__ void transpose_h(const float* __restrict__ src, __half* __restrict__ dst,
                            int K, int N) {
    __shared__ float s[32][33];
    int n0 = blockIdx.x * 32, k0 = blockIdx.y * 32;
    int tx = threadIdx.x, ty = threadIdx.y;
#pragma unroll
    for (int i = 0; i < 4; ++i)
        s[ty + 8 * i][tx] = src[(size_t)(k0 + ty + 8 * i) * N + n0 + tx];
    __syncthreads();
#pragma unroll
    for (int i = 0; i < 4; ++i)
        dst[(size_t)(n0 + ty + 8 * i) * K + k0 + tx] = __float2half_rn(s[tx][ty + 8 * i]);
}

// pool(16) + RMSNorm + gelu -> half scratch
__global__ void __launch_bounds__(384) pool_norm_kernel(const float* __restrict__ x,
                                                        const float* __restrict__ scale) {
    int row = blockIdx.x;
    int t = threadIdx.x;
    const float* xr = x + (size_t)row * 16 * Dd;
    float pooled[4];
    float ss = 0.f;
#pragma unroll
    for (int u = 0; u < 4; ++u) {
        int d = t + u * 384;
        float s = 0.f;
#pragma unroll
        for (int j = 0; j < 16; ++j) s += xr[(size_t)j * Dd + d];
        s *= 0.0625f;
        pooled[u] = s;
        ss += s * s;
    }
    __shared__ float red[13];
#pragma unroll
    for (int o = 16; o; o >>= 1) ss += __shfl_xor_sync(0xffffffffu, ss, o);
    if ((t & 31) == 0) red[t >> 5] = ss;
    __syncthreads();
    if (t == 0) {
        float tot = 0.f;
        for (int i = 0; i < 12; ++i) tot += red[i];
        red[12] = rsqrtf(tot * (1.f / 1536.f) + 1e-5f);
    }
    __syncthreads();
    float inv = red[12];
#pragma unroll
    for (int u = 0; u < 4; ++u) {
        int d = t + u * 384;
        float v = pooled[u] * inv * scale[d];
        g_xph[(size_t)row * Dd + d] = __float2half_rn(v);
        float v3 = v * v * v;
        float gl = 0.5f * v * (1.f + tanhf(0.7978845608028654f * (v + 0.044715f * v3)));
        g_gh[(size_t)row * Dd + d] = __float2half_rn(gl);
    }
}

__global__ void suffix_kernel(const float* __restrict__ wpos) {
    int hc = blockIdx.x * 256 + threadIdx.x;
    float aq = 0.f, as = 0.f;
    for (int f = Ff - 1; f >= 0; --f) {
        aq += wpos[f * HC + hc];
        as += wpos[(Ff + f) * HC + hc];
        g_sufq[f * HC + hc] = aq;
        g_sufs[f * HC + hc] = as;
    }
}

__global__ void __launch_bounds__(256) posenc_kernel(const float* __restrict__ bpos) {
    int p = blockIdx.x;
    int hc4 = (blockIdx.y * 256 + threadIdx.x) * 4;
    int dist = (p >= 512) ? p - 512 : 512 - p;
    int fm = g_fmin[dist];
    float4 v = *(const float4*)&bpos[hc4];
    if (fm < 32) {
        float sg = (p > 512) ? 1.f : ((p < 512) ? -1.f : 0.f);
        float4 a = *(const float4*)&g_sufq[fm * HC + hc4];
        float4 s = *(const float4*)&g_sufs[fm * HC + hc4];
        v.x += a.x + sg * s.x; v.y += a.y + sg * s.y;
        v.z += a.z + sg * s.z; v.w += a.w + sg * s.w;
    }
    __half2* dst = (__half2*)&g_posh[(size_t)p * HC + hc4];
    dst[0] = h2(v.x, v.y);
    dst[1] = h2(v.z, v.w);
}

__global__ void reduce_y_kernel() {
    int i = blockIdx.x * 256 + threadIdx.x;
    float sq = 0.f, sk = 0.f;
#pragma unroll
    for (int s = 0; s < 8; ++s) {
        sq += g_ypart[s * 131072 + i];
        sk += g_ypart[(8 + s) * 131072 + i];
    }
    g_yq[i] = sq;
    g_yk[i] = sk;
}

// ---------------- q/k projections: C = xp @ W^T (NT, fp16 mma, 64-K stages) ----------------
__global__ void __launch_bounds__(256, 2) proj_tc(const float* __restrict__ qrb,
                                                  const float* __restrict__ krb) {
    extern __shared__ __half sh[];
    Tile AsT[2] = {(Tile)sh, (Tile)(sh + 128 * TW)};
    Tile BsT[2] = {(Tile)(sh + 2 * 128 * TW), (Tile)(sh + 3 * 128 * TW)};
    int sel = blockIdx.z;
    const __half* Bt = sel ? g_wkt : g_wqt;
    __half* Oq = sel ? g_kh : g_qh;
    __half* Ob = sel ? g_kbh : g_qbh;
    const float* bias = sel ? krb : qrb;
    int m0 = blockIdx.y * 128, n0 = blockIdx.x * 128;
    int t = threadIdx.x, lane = t & 31, wid = t >> 5;
    int grp = lane >> 2, tig = lane & 3;
    int moff = (wid >> 2) * 64, noff = (wid & 3) * 32;
    float acc[4][4][4] = {};
    const __half* Ab = g_xph + (size_t)m0 * Dd;
    const __half* Bp = Bt + (size_t)n0 * Dd;
    cp_tile64(AsT[0], Ab, Dd, t);
    cp_tile64(BsT[0], Bp, Dd, t);
    CPCOMMIT();
    for (int ib = 0; ib < 24; ++ib) {
        CPWAIT0();
        __syncthreads();
        if (ib < 23) {
            int st = (ib + 1) & 1, kb = (ib + 1) * 64;
            cp_tile64(AsT[st], Ab + kb, Dd, t);
            cp_tile64(BsT[st], Bp + kb, Dd, t);
            CPCOMMIT();
        }
        Tile As_ = AsT[ib & 1], Bs_ = BsT[ib & 1];
        STAGE_MMA64(As_, Bs_);
        __syncthreads();
    }
#pragma unroll
    for (int mi = 0; mi < 4; ++mi) {
        int r = m0 + moff + 16 * mi + grp;
#pragma unroll
        for (int ni = 0; ni < 4; ++ni) {
            int c = n0 + noff + 8 * ni + 2 * tig;
            float2 bv = *(const float2*)&bias[c];
            size_t o0 = (size_t)r * HC + c, o1 = (size_t)(r + 8) * HC + c;
            *(__half2*)&Oq[o0] = h2(acc[mi][ni][0], acc[mi][ni][1]);
            *(__half2*)&Oq[o1] = h2(acc[mi][ni][2], acc[mi][ni][3]);
            *(__half2*)&Ob[o0] = h2(acc[mi][ni][0] + bv.x, acc[mi][ni][1] + bv.y);
            *(__half2*)&Ob[o1] = h2(acc[mi][ni][2] + bv.x, acc[mi][ni][3] + bv.y);
        }
    }
}

// ---------------- y projections (k-split 192, NT fp16) ----------------
__global__ void __launch_bounds__(256, 2) ygemm_tc() {
    extern __shared__ __half sh[];
    Tile AsT[2] = {(Tile)sh, (Tile)(sh + 128 * TW)};
    Tile BsT[2] = {(Tile)(sh + 2 * 128 * TW), (Tile)(sh + 3 * 128 * TW)};
    int z = blockIdx.z;
    int side = z >> 3, slice = z & 7;
    const __half* Bt = side ? g_wykt : g_wyqt;
    int m0 = blockIdx.y * 128;
    int kstart = slice * 192;
    int t = threadIdx.x, lane = t & 31, wid = t >> 5;
    int grp = lane >> 2, tig = lane & 3;
    int moff = (wid >> 2) * 64, noff = (wid & 3) * 32;
    float acc[4][4][4] = {};
    const __half* Ab = g_gh + (size_t)m0 * Dd + kstart;
    const __half* Bp = Bt + kstart;
    cp_tile64(AsT[0], Ab, Dd, t);
    cp_tile64(BsT[0], Bp, Dd, t);
    CPCOMMIT();
    for (int ib = 0; ib < 3; ++ib) {
        CPWAIT0();
        __syncthreads();
        if (ib < 2) {
            int st = (ib + 1) & 1, kb = (ib + 1) * 64;
            cp_tile64(AsT[st], Ab + kb, Dd, t);
            cp_tile64(BsT[st], Bp + kb, Dd, t);
            CPCOMMIT();
        }
        Tile As_ = AsT[ib & 1], Bs_ = BsT[ib & 1];
        STAGE_MMA64(As_, Bs_);
        __syncthreads();
    }
    float* Cp = g_ypart + (size_t)z * 131072;
#pragma unroll
    for (int mi = 0; mi < 4; ++mi) {
        int r = m0 + moff + 16 * mi + grp;
#pragma unroll
        for (int ni = 0; ni < 4; ++ni) {
            int c = noff + 8 * ni + 2 * tig;
            *(float2*)&Cp[(size_t)r * 128 + c] = make_float2(acc[mi][ni][0], acc[mi][ni][1]);
            *(float2*)&Cp[(size_t)(r + 8) * 128 + c] = make_float2(acc[mi][ni][2], acc[mi][ni][3]);
        }
    }
}

// ---------------- rel logits (NT, band-restricted, fp16, half output) ----------------
__global__ void __launch_bounds__(256, 2) rel_tc() {
    extern __shared__ __half sh[];
    Tile AsT[2] = {(Tile)sh, (Tile)(sh + 128 * TW)};
    Tile BsT[2] = {(Tile)(sh + 2 * 128 * TW), (Tile)(sh + 3 * 128 * TW)};
    int z = blockIdx.z;
    int side = z >> 6, bh = z & 63, b = bh >> 5, h = bh & 31;
    const __half* A  = (side ? g_kbh : g_qbh) + (size_t)b * Ss * HC + h * Cc;
    const __half* Bt = g_posh + h * Cc;
    __half* Cp = (side ? g_rkh : g_rqh) + (size_t)bh * (Ss * P2);
    int my = blockIdx.y;
    int m0 = my * 128;
    int n0 = (blockIdx.x + 3 - my) * 128;
    int t = threadIdx.x, lane = t & 31, wid = t >> 5;
    int grp = lane >> 2, tig = lane & 3;
    int moff = (wid >> 2) * 64, noff = (wid & 3) * 32;
    float acc[4][4][4] = {};
    const __half* Ab = A + (size_t)m0 * HC;
    const __half* Bp = Bt + (size_t)n0 * HC;
    cp_tile64(AsT[0], Ab, HC, t);
    cp_tile64(BsT[0], Bp, HC, t);
    CPCOMMIT();
    for (int ib = 0; ib < 2; ++ib) {
        CPWAIT0();
        __syncthreads();
        if (ib < 1) {
            cp_tile64(AsT[1], Ab + 64, HC, t);
            cp_tile64(BsT[1], Bp + 64, HC, t);
            CPCOMMIT();
        }
        Tile As_ = AsT[ib & 1], Bs_ = BsT[ib & 1];
        STAGE_MMA64(As_, Bs_);
        __syncthreads();
    }
#pragma unroll
    for (int mi = 0; mi < 4; ++mi) {
        int r = m0 + moff + 16 * mi + grp;
#pragma unroll
        for (int ni = 0; ni < 4; ++ni) {
            int c = n0 + noff + 8 * ni + 2 * tig;
            *(__half2*)&Cp[(size_t)r * P2 + c] = h2(acc[mi][ni][0], acc[mi][ni][1]);
            *(__half2*)&Cp[(size_t)(r + 8) * P2 + c] = h2(acc[mi][ni][2], acc[mi][ni][3]);
        }
    }
}

// ---------------- a = QK^T + 0.5*(rq + rk gathers), writes half ----------------
__global__ void __launch_bounds__(256, 2) a_tc() {
    extern __shared__ __half sh[];
    Tile AsT[2] = {(Tile)sh, (Tile)(sh + 128 * TW)};
    Tile BsT[2] = {(Tile)(sh + 2 * 128 * TW), (Tile)(sh + 3 * 128 * TW)};
    int bh = blockIdx.z, b = bh >> 5, h = bh & 31;
    const __half* A  = g_qh + (size_t)b * Ss * HC + h * Cc;
    const __half* Bt = g_kh + (size_t)b * Ss * HC + h * Cc;
    const __half* rqb = g_rqh + (size_t)bh * (Ss * P2);
    const __half* rkb = g_rkh + (size_t)bh * (Ss * P2);
    __half* Cp = g_ah + (size_t)bh * (Ss * Ss);
    int m0 = blockIdx.y * 128, n0 = blockIdx.x * 128;
    int t = threadIdx.x, lane = t & 31, wid = t >> 5;
    int grp = lane >> 2, tig = lane & 3;
    int moff = (wid >> 2) * 64, noff = (wid & 3) * 32;
    float acc[4][4][4] = {};
    const __half* Ab = A + (size_t)m0 * HC;
    const __half* Bp = Bt + (size_t)n0 * HC;
    cp_tile64(AsT[0], Ab, HC, t);
    cp_tile64(BsT[0], Bp, HC, t);
    CPCOMMIT();
    for (int ib = 0; ib < 2; ++ib) {
        CPWAIT0();
        __syncthreads();
        if (ib < 1) {
            cp_tile64(AsT[1], Ab + 64, HC, t);
            cp_tile64(BsT[1], Bp + 64, HC, t);
            CPCOMMIT();
        }
        Tile As_ = AsT[ib & 1], Bs_ = BsT[ib & 1];
        STAGE_MMA64(As_, Bs_);
        __syncthreads();
    }
#pragma unroll
    for (int mi = 0; mi < 4; ++mi) {
        int q0 = m0 + moff + 16 * mi + grp;
#pragma unroll
        for (int ni = 0; ni < 4; ++ni) {
            int kg = n0 + noff + 8 * ni + 2 * tig;
            float rq00 = __half2float(rqb[(size_t)q0 * P2 + kg - q0 + 512]);
            float rq01 = __half2float(rqb[(size_t)q0 * P2 + kg + 1 - q0 + 512]);
            float rq10 = __half2float(rqb[(size_t)(q0 + 8) * P2 + kg - q0 - 8 + 512]);
            float rq11 = __half2float(rqb[(size_t)(q0 + 8) * P2 + kg + 1 - q0 - 8 + 512]);
            float rk00 = __half2float(rkb[(size_t)kg * P2 + q0 - kg + 512]);
            float rk01 = __half2float(rkb[(size_t)(kg + 1) * P2 + q0 - kg - 1 + 512]);
            float rk10 = __half2float(rkb[(size_t)kg * P2 + q0 + 8 - kg + 512]);
            float rk11 = __half2float(rkb[(size_t)(kg + 1) * P2 + q0 + 7 - kg + 512]);
            *(__half2*)&Cp[(size_t)q0 * Ss + kg] =
                h2(acc[mi][ni][0] + 0.5f * (rq00 + rk00),
                   acc[mi][ni][1] + 0.5f * (rq01 + rk01));
            *(__half2*)&Cp[(size_t)(q0 + 8) * Ss + kg] =
                h2(acc[mi][ni][2] + 0.5f * (rq10 + rk10),
                   acc[mi][ni][3] + 0.5f * (rq11 + rk11));
        }
    }
}

// ---------------- final: out = a(h) @ w_pair + b_pair + yq + yk ----------------
__global__ void __launch_bounds__(256) final_tc(const float* __restrict__ bpair,
                                                float* __restrict__ out) {
    __shared__ __half At_s[128][34];
    __shared__ __half Ws[128][40];
    __shared__ float basef[128];
    int k0 = blockIdx.x * 128, q = blockIdx.y, b = blockIdx.z;
    int t = threadIdx.x, lane = t & 31, wid = t >> 5;
    int grp = lane >> 2, tig = lane & 3;
    int moff = (wid >> 2) * 64, noff = (wid & 3) * 32;
#pragma unroll
    for (int i = 0; i < 2; ++i) {
        int c = t + 256 * i;
        int r = c >> 2, c16 = (c & 3) * 8;
        cpa16(&Ws[r][c16], g_wpt + (size_t)r * 32 + c16);
    }
    CPCOMMIT();
#pragma unroll
    for (int it = 0; it < 8; ++it) {
        int id = t + 256 * it;
        int hh = id >> 6, j = id & 63;
        __half2 v = *(const __half2*)&g_ah[(((size_t)(b * 32 + hh) * Ss + q) * Ss) + k0 + 2 * j];
        At_s[2 * j][hh] = __low2half(v);
        At_s[2 * j + 1][hh] = __high2half(v);
    }
    if (t < 128) basef[t] = bpair[t] + g_yq[(size_t)(b * 512 + q) * 128 + t];
    CPWAIT0();
    __syncthreads();
    float acc[4][4][4] = {};
#pragma unroll
    for (int ks = 0; ks < 2; ++ks) {
        int koff = ks * 16 + 2 * tig;
        uint32_t af[4][4], bf[4][2];
#pragma unroll
        for (int mi = 0; mi < 4; ++mi) {
            int r = moff + 16 * mi + grp;
            af[mi][0] = *(const uint32_t*)&At_s[r][koff];
            af[mi][1] = *(const uint32_t*)&At_s[r + 8][koff];
            af[mi][2] = *(const uint32_t*)&At_s[r][koff + 8];
            af[mi][3] = *(const uint32_t*)&At_s[r + 8][koff + 8];
        }
#pragma unroll
        for (int ni = 0; ni < 4; ++ni) {
            int c = noff + 8 * ni + grp;
            bf[ni][0] = *(const uint32_t*)&Ws[c][koff];
            bf[ni][1] = *(const uint32_t*)&Ws[c][koff + 8];
        }
#pragma unroll
        for (int mi = 0; mi < 4; ++mi)
#pragma unroll
            for (int ni = 0; ni < 4; ++ni) MMA_F16(acc[mi][ni], af[mi], bf[ni]);
    }
#pragma unroll
    for (int mi = 0; mi < 4; ++mi) {
        int kl0 = moff + 16 * mi + grp;
        size_t row0 = ((size_t)(b * 512 + q) * 512 + k0 + kl0) * 128;
        size_t row1 = row0 + (size_t)8 * 128;
        const float* yk0 = &g_yk[(size_t)(b * 512 + k0 + kl0) * 128];
        const float* yk1 = yk0 + 8 * 128;
#pragma unroll
        for (int ni = 0; ni < 4; ++ni) {
            int f = noff + 8 * ni + 2 * tig;
            float2 y0 = *(const float2*)&yk0[f];
            float2 y1 = *(const float2*)&yk1[f];
            *(float2*)&out[row0 + f] = make_float2(acc[mi][ni][0] + basef[f] + y0.x,
                                                   acc[mi][ni][1] + basef[f + 1] + y0.y);
            *(float2*)&out[row1 + f] = make_float2(acc[mi][ni][2] + basef[f] + y1.x,
                                                   acc[mi][ni][3] + basef[f + 1] + y1.y);
        }
    }
}

// ---------------- launcher ----------------
extern "C" void kernel_launch(void* const* d_in, const int* in_sizes, int n_in,
                              void* d_out, int out_size) {
    const float* x        = (const float*)d_in[0];
    const float* scale    = (const float*)d_in[1];
    const float* w_q      = (const float*)d_in[2];
    const float* w_k      = (const float*)d_in[3];
    const float* w_pos    = (const float*)d_in[4];
    const float* b_pos    = (const float*)d_in[5];
    const float* q_r_bias = (const float*)d_in[6];
    const float* k_r_bias = (const float*)d_in[7];
    const float* w_yq     = (const float*)d_in[8];
    const float* w_yk     = (const float*)d_in[9];
    const float* w_pair   = (const float*)d_in[10];
    const float* b_pair   = (const float*)d_in[11];
    float* out = (float*)d_out;

    __half *p_wqt, *p_wkt, *p_wyqt, *p_wykt, *p_wpt;
    cudaGetSymbolAddress((void**)&p_wqt, g_wqt);
    cudaGetSymbolAddress((void**)&p_wkt, g_wkt);
    cudaGetSymbolAddress((void**)&p_wyqt, g_wyqt);
    cudaGetSymbolAddress((void**)&p_wykt, g_wykt);
    cudaGetSymbolAddress((void**)&p_wpt, g_wpt);

    cudaFuncSetAttribute(proj_tc, cudaFuncAttributeMaxDynamicSharedMemorySize, SMEMB);
    cudaFuncSetAttribute(ygemm_tc, cudaFuncAttributeMaxDynamicSharedMemorySize, SMEMB);
    cudaFuncSetAttribute(rel_tc, cudaFuncAttributeMaxDynamicSharedMemorySize, SMEMB);
    cudaFuncSetAttribute(a_tc, cudaFuncAttributeMaxDynamicSharedMemorySize, SMEMB);

    init_cw_kernel<<<1, 32>>>();
    fmin_kernel<<<5, 128>>>();
    transpose_h<<<dim3(128, 48), dim3(32, 8)>>>(w_q, p_wqt, Dd, HC);
    transpose_h<<<dim3(128, 48), dim3(32, 8)>>>(w_k, p_wkt, Dd, HC);
    transpose_h<<<dim3(4, 48), dim3(32, 8)>>>(w_yq, p_wyqt, Dd, PAIRF);
    transpose_h<<<dim3(4, 48), dim3(32, 8)>>>(w_yk, p_wykt, Dd, PAIRF);
    transpose_h<<<dim3(4, 1), dim3(32, 8)>>>(w_pair, p_wpt, Hh, PAIRF);
    pool_norm_kernel<<<1024, 384>>>(x, scale);
    suffix_kernel<<<16, 256>>>(w_pos);
    posenc_kernel<<<dim3(1024, 4), 256>>>(b_pos);
    proj_tc<<<dim3(32, 8, 2), 256, SMEMB>>>(q_r_bias, k_r_bias);
    ygemm_tc<<<dim3(1, 8, 16), 256, SMEMB>>>();
    reduce_y_kernel<<<512, 256>>>();
    rel_tc<<<dim3(5, 4, 128), 256, SMEMB>>>();
    a_tc<<<dim3(4, 4, 64), 256, SMEMB>>>();
    final_tc<<<dim3(4, 512, 2), 256>>>(b_pair, out);
}

// round 8
// speedup vs baseline: 4.3595x; 1.0590x over previous
#include <cuda_runtime.h>
#include <cuda_fp16.h>
#include <math.h>
#include <stdint.h>

#define Bb 2
#define Dd 1536
#define Ss 512
#define Hh 32
#define Cc 128
#define HC 4096
#define Ff 32
#define PAIRF 128
#define P2 1024
#define TW 72   // smem tile row width (halfs); 144B row stride -> conflict-free LDSM

// ---------------- scratch (device globals) ----------------
__device__ __half g_xph[Bb*Ss*Dd];
__device__ __half g_gh [Bb*Ss*Dd];
__device__ __half g_qh [Bb*Ss*HC];
__device__ __half g_kh [Bb*Ss*HC];
__device__ __half g_qbh[Bb*Ss*HC];
__device__ __half g_kbh[Bb*Ss*HC];
__device__ __half g_posh[P2*HC];
__device__ __half g_wqt[HC*Dd];
__device__ __half g_wkt[HC*Dd];
__device__ __half g_wyqt[PAIRF*Dd];
__device__ __half g_wykt[PAIRF*Dd];
__device__ __half g_wpt[PAIRF*Hh];
__device__ __half g_ah[(size_t)Bb*Hh*Ss*Ss];
__device__ __half g_rqh[(size_t)Bb*Hh*Ss*P2];
__device__ __half g_rkh[(size_t)Bb*Hh*Ss*P2];
__device__ float g_sufq[Ff*HC];
__device__ float g_sufs[Ff*HC];
__device__ float g_cw[Ff];
__device__ int   g_fmin[513];
__device__ float g_yq[Bb*Ss*PAIRF];
__device__ float g_yk[Bb*Ss*PAIRF];
__device__ float g_ypart[16*Bb*Ss*PAIRF];

// ---------------- helpers ----------------
__device__ __forceinline__ __half2 h2(float a, float b) {
    return __halves2half2(__float2half_rn(a), __float2half_rn(b));
}

#define MMA_F16(d, a, b) asm volatile( \
    "mma.sync.aligned.m16n8k16.row.col.f32.f16.f16.f32 " \
    "{%0,%1,%2,%3}, {%4,%5,%6,%7}, {%8,%9}, {%0,%1,%2,%3};\n" \
    : "+f"((d)[0]), "+f"((d)[1]), "+f"((d)[2]), "+f"((d)[3]) \
    : "r"((a)[0]), "r"((a)[1]), "r"((a)[2]), "r"((a)[3]), \
      "r"((b)[0]), "r"((b)[1]))

__device__ __forceinline__ void cpa16(void* dst, const void* src) {
    uint32_t d = (uint32_t)__cvta_generic_to_shared(dst);
    asm volatile("cp.async.ca.shared.global [%0], [%1], 16;\n" :: "r"(d), "l"(src));
}
#define CPCOMMIT() asm volatile("cp.async.commit_group;\n")
#define CPWAIT0()  asm volatile("cp.async.wait_group 0;\n")

__device__ __forceinline__ uint32_t smem_u32(const void* p) {
    uint32_t a;
    asm("{ .reg .u64 t; cvta.to.shared.u64 t, %1; cvt.u32.u64 %0, t; }" : "=r"(a) : "l"(p));
    return a;
}

__device__ __forceinline__ void ldsm_x4(uint32_t* r, uint32_t addr) {
    asm volatile("ldmatrix.sync.aligned.m8n8.x4.shared.b16 {%0,%1,%2,%3}, [%4];"
        : "=r"(r[0]), "=r"(r[1]), "=r"(r[2]), "=r"(r[3]) : "r"(addr));
}

typedef __half (*Tile)[TW];

// stage a 128-row x 64-half tile into smem [128][TW]
__device__ __forceinline__ void cp_tile64(Tile dst, const __half* src, int ld, int t) {
#pragma unroll
    for (int i = 0; i < 4; ++i) {
        int c = t + 256 * i;
        int r = c >> 3, c16 = (c & 7) * 8;
        cpa16(&dst[r][c16], src + (size_t)r * ld + c16);
    }
}

// fragment compute for one 64-K stage via ldmatrix (4 k-steps of 16)
// aA/aB: smem byte addresses of As_[moff + (lane&15)][(lane>>4)*8] and
//        Bs_[noff + (lane&15)][(lane>>4)*8] for the CURRENT buffer.
#define STAGE_MMA64_LDSM(aA, aB)                                               \
    _Pragma("unroll")                                                          \
    for (int ks = 0; ks < 4; ++ks) {                                           \
        uint32_t af[4][4], bq[2][4];                                           \
        _Pragma("unroll")                                                      \
        for (int mi = 0; mi < 4; ++mi)                                         \
            ldsm_x4(af[mi], (aA) + mi * (16 * TW * 2) + ks * 32);              \
        _Pragma("unroll")                                                      \
        for (int p = 0; p < 2; ++p)                                            \
            ldsm_x4(bq[p], (aB) + p * (16 * TW * 2) + ks * 32);                \
        _Pragma("unroll")                                                      \
        for (int mi = 0; mi < 4; ++mi) {                                       \
            _Pragma("unroll")                                                  \
            for (int p = 0; p < 2; ++p) {                                      \
                uint32_t b0[2] = {bq[p][0], bq[p][2]};                         \
                uint32_t b1[2] = {bq[p][1], bq[p][3]};                         \
                MMA_F16(acc[mi][2 * p], af[mi], b0);                           \
                MMA_F16(acc[mi][2 * p + 1], af[mi], b1);                       \
            }                                                                  \
        }                                                                      \
    }

#define SMEMB (4 * 128 * TW * 2)   // 73728 bytes

// ---------------- small init kernels ----------------
__global__ void init_cw_kernel() {
    int f = threadIdx.x;
    if (f < Ff)
        g_cw[f] = (float)((double)f + exp(log(481.0) * ((double)f / 32.0)));
}

__global__ void fmin_kernel() {
    int d = blockIdx.x * 128 + threadIdx.x;
    if (d <= 512) {
        int fm = 32;
        for (int f = 31; f >= 0; --f)
            if (g_cw[f] > (float)d) fm = f;
        g_fmin[d] = fm;
    }
}

__global__ void transpose_h(const float* __restrict__ src, __half* __restrict__ dst,
                            int K, int N) {
    __shared__ float s[32][33];
    int n0 = blockIdx.x * 32, k0 = blockIdx.y * 32;
    int tx = threadIdx.x, ty = threadIdx.y;
#pragma unroll
    for (int i = 0; i < 4; ++i)
        s[ty + 8 * i][tx] = src[(size_t)(k0 + ty + 8 * i) * N + n0 + tx];
    __syncthreads();
#pragma unroll
    for (int i = 0; i < 4; ++i)
        dst[(size_t)(n0 + ty + 8 * i) * K + k0 + tx] = __float2half_rn(s[tx][ty + 8 * i]);
}

__global__ void __launch_bounds__(384) pool_norm_kernel(const float* __restrict__ x,
                                                        const float* __restrict__ scale) {
    int row = blockIdx.x;
    int t = threadIdx.x;
    const float* xr = x + (size_t)row * 16 * Dd;
    float pooled[4];
    float ss = 0.f;
#pragma unroll
    for (int u = 0; u < 4; ++u) {
        int d = t + u * 384;
        float s = 0.f;
#pragma unroll
        for (int j = 0; j < 16; ++j) s += xr[(size_t)j * Dd + d];
        s *= 0.0625f;
        pooled[u] = s;
        ss += s * s;
    }
    __shared__ float red[13];
#pragma unroll
    for (int o = 16; o; o >>= 1) ss += __shfl_xor_sync(0xffffffffu, ss, o);
    if ((t & 31) == 0) red[t >> 5] = ss;
    __syncthreads();
    if (t == 0) {
        float tot = 0.f;
        for (int i = 0; i < 12; ++i) tot += red[i];
        red[12] = rsqrtf(tot * (1.f / 1536.f) + 1e-5f);
    }
    __syncthreads();
    float inv = red[12];
#pragma unroll
    for (int u = 0; u < 4; ++u) {
        int d = t + u * 384;
        float v = pooled[u] * inv * scale[d];
        g_xph[(size_t)row * Dd + d] = __float2half_rn(v);
        float v3 = v * v * v;
        float gl = 0.5f * v * (1.f + tanhf(0.7978845608028654f * (v + 0.044715f * v3)));
        g_gh[(size_t)row * Dd + d] = __float2half_rn(gl);
    }
}

__global__ void suffix_kernel(const float* __restrict__ wpos) {
    int hc = blockIdx.x * 256 + threadIdx.x;
    float aq = 0.f, as = 0.f;
    for (int f = Ff - 1; f >= 0; --f) {
        aq += wpos[f * HC + hc];
        as += wpos[(Ff + f) * HC + hc];
        g_sufq[f * HC + hc] = aq;
        g_sufs[f * HC + hc] = as;
    }
}

__global__ void __launch_bounds__(256) posenc_kernel(const float* __restrict__ bpos) {
    int p = blockIdx.x;
    int hc4 = (blockIdx.y * 256 + threadIdx.x) * 4;
    int dist = (p >= 512) ? p - 512 : 512 - p;
    int fm = g_fmin[dist];
    float4 v = *(const float4*)&bpos[hc4];
    if (fm < 32) {
        float sg = (p > 512) ? 1.f : ((p < 512) ? -1.f : 0.f);
        float4 a = *(const float4*)&g_sufq[fm * HC + hc4];
        float4 s = *(const float4*)&g_sufs[fm * HC + hc4];
        v.x += a.x + sg * s.x; v.y += a.y + sg * s.y;
        v.z += a.z + sg * s.z; v.w += a.w + sg * s.w;
    }
    __half2* dst = (__half2*)&g_posh[(size_t)p * HC + hc4];
    dst[0] = h2(v.x, v.y);
    dst[1] = h2(v.z, v.w);
}

__global__ void reduce_y_kernel() {
    int i = blockIdx.x * 256 + threadIdx.x;
    float sq = 0.f, sk = 0.f;
#pragma unroll
    for (int s = 0; s < 8; ++s) {
        sq += g_ypart[s * 131072 + i];
        sk += g_ypart[(8 + s) * 131072 + i];
    }
    g_yq[i] = sq;
    g_yk[i] = sk;
}

// ---------------- q/k projections: C = xp @ W^T (NT, fp16 mma, 64-K stages) ----------------
__global__ void __launch_bounds__(256, 2) proj_tc(const float* __restrict__ qrb,
                                                  const float* __restrict__ krb) {
    extern __shared__ __half sh[];
    Tile AsT[2] = {(Tile)sh, (Tile)(sh + 128 * TW)};
    Tile BsT[2] = {(Tile)(sh + 2 * 128 * TW), (Tile)(sh + 3 * 128 * TW)};
    int sel = blockIdx.z;
    const __half* Bt = sel ? g_wkt : g_wqt;
    __half* Oq = sel ? g_kh : g_qh;
    __half* Ob = sel ? g_kbh : g_qbh;
    const float* bias = sel ? krb : qrb;
    int m0 = blockIdx.y * 128, n0 = blockIdx.x * 128;
    int t = threadIdx.x, lane = t & 31, wid = t >> 5;
    int grp = lane >> 2, tig = lane & 3;
    int moff = (wid >> 2) * 64, noff = (wid & 3) * 32;
    int lrow = lane & 15, lcol = (lane >> 4) * 8;
    uint32_t aA0 = smem_u32(&AsT[0][moff + lrow][lcol]);
    uint32_t aB0 = smem_u32(&BsT[0][noff + lrow][lcol]);
    const uint32_t bufo = 128 * TW * 2;
    float acc[4][4][4] = {};
    const __half* Ab = g_xph + (size_t)m0 * Dd;
    const __half* Bp = Bt + (size_t)n0 * Dd;
    cp_tile64(AsT[0], Ab, Dd, t);
    cp_tile64(BsT[0], Bp, Dd, t);
    CPCOMMIT();
    for (int ib = 0; ib < 24; ++ib) {
        CPWAIT0();
        __syncthreads();
        if (ib < 23) {
            int st = (ib + 1) & 1, kb = (ib + 1) * 64;
            cp_tile64(AsT[st], Ab + kb, Dd, t);
            cp_tile64(BsT[st], Bp + kb, Dd, t);
            CPCOMMIT();
        }
        uint32_t off = (ib & 1) * bufo;
        STAGE_MMA64_LDSM(aA0 + off, aB0 + off);
        __syncthreads();
    }
#pragma unroll
    for (int mi = 0; mi < 4; ++mi) {
        int r = m0 + moff + 16 * mi + grp;
#pragma unroll
        for (int ni = 0; ni < 4; ++ni) {
            int c = n0 + noff + 8 * ni + 2 * tig;
            float2 bv = *(const float2*)&bias[c];
            size_t o0 = (size_t)r * HC + c, o1 = (size_t)(r + 8) * HC + c;
            *(__half2*)&Oq[o0] = h2(acc[mi][ni][0], acc[mi][ni][1]);
            *(__half2*)&Oq[o1] = h2(acc[mi][ni][2], acc[mi][ni][3]);
            *(__half2*)&Ob[o0] = h2(acc[mi][ni][0] + bv.x, acc[mi][ni][1] + bv.y);
            *(__half2*)&Ob[o1] = h2(acc[mi][ni][2] + bv.x, acc[mi][ni][3] + bv.y);
        }
    }
}

// ---------------- y projections (k-split 192, NT fp16) ----------------
__global__ void __launch_bounds__(256, 2) ygemm_tc() {
    extern __shared__ __half sh[];
    Tile AsT[2] = {(Tile)sh, (Tile)(sh + 128 * TW)};
    Tile BsT[2] = {(Tile)(sh + 2 * 128 * TW), (Tile)(sh + 3 * 128 * TW)};
    int z = blockIdx.z;
    int side = z >> 3, slice = z & 7;
    const __half* Bt = side ? g_wykt : g_wyqt;
    int m0 = blockIdx.y * 128;
    int kstart = slice * 192;
    int t = threadIdx.x, lane = t & 31, wid = t >> 5;
    int grp = lane >> 2, tig = lane & 3;
    int moff = (wid >> 2) * 64, noff = (wid & 3) * 32;
    int lrow = lane & 15, lcol = (lane >> 4) * 8;
    uint32_t aA0 = smem_u32(&AsT[0][moff + lrow][lcol]);
    uint32_t aB0 = smem_u32(&BsT[0][noff + lrow][lcol]);
    const uint32_t bufo = 128 * TW * 2;
    float acc[4][4][4] = {};
    const __half* Ab = g_gh + (size_t)m0 * Dd + kstart;
    const __half* Bp = Bt + kstart;
    cp_tile64(AsT[0], Ab, Dd, t);
    cp_tile64(BsT[0], Bp, Dd, t);
    CPCOMMIT();
    for (int ib = 0; ib < 3; ++ib) {
        CPWAIT0();
        __syncthreads();
        if (ib < 2) {
            int st = (ib + 1) & 1, kb = (ib + 1) * 64;
            cp_tile64(AsT[st], Ab + kb, Dd, t);
            cp_tile64(BsT[st], Bp + kb, Dd, t);
            CPCOMMIT();
        }
        uint32_t off = (ib & 1) * bufo;
        STAGE_MMA64_LDSM(aA0 + off, aB0 + off);
        __syncthreads();
    }
    float* Cp = g_ypart + (size_t)z * 131072;
#pragma unroll
    for (int mi = 0; mi < 4; ++mi) {
        int r = m0 + moff + 16 * mi + grp;
#pragma unroll
        for (int ni = 0; ni < 4; ++ni) {
            int c = noff + 8 * ni + 2 * tig;
            *(float2*)&Cp[(size_t)r * 128 + c] = make_float2(acc[mi][ni][0], acc[mi][ni][1]);
            *(float2*)&Cp[(size_t)(r + 8) * 128 + c] = make_float2(acc[mi][ni][2], acc[mi][ni][3]);
        }
    }
}

// ---------------- rel logits (NT, band-restricted, fp16, half output) ----------------
__global__ void __launch_bounds__(256, 2) rel_tc() {
    extern __shared__ __half sh[];
    Tile AsT[2] = {(Tile)sh, (Tile)(sh + 128 * TW)};
    Tile BsT[2] = {(Tile)(sh + 2 * 128 * TW), (Tile)(sh + 3 * 128 * TW)};
    int z = blockIdx.z;
    int side = z >> 6, bh = z & 63, b = bh >> 5, h = bh & 31;
    const __half* A  = (side ? g_kbh : g_qbh) + (size_t)b * Ss * HC + h * Cc;
    const __half* Bt = g_posh + h * Cc;
    __half* Cp = (side ? g_rkh : g_rqh) + (size_t)bh * (Ss * P2);
    int my = blockIdx.y;
    int m0 = my * 128;
    int n0 = (blockIdx.x + 3 - my) * 128;
    int t = threadIdx.x, lane = t & 31, wid = t >> 5;
    int grp = lane >> 2, tig = lane & 3;
    int moff = (wid >> 2) * 64, noff = (wid & 3) * 32;
    int lrow = lane & 15, lcol = (lane >> 4) * 8;
    uint32_t aA0 = smem_u32(&AsT[0][moff + lrow][lcol]);
    uint32_t aB0 = smem_u32(&BsT[0][noff + lrow][lcol]);
    const uint32_t bufo = 128 * TW * 2;
    float acc[4][4][4] = {};
    const __half* Ab = A + (size_t)m0 * HC;
    const __half* Bp = Bt + (size_t)n0 * HC;
    cp_tile64(AsT[0], Ab, HC, t);
    cp_tile64(BsT[0], Bp, HC, t);
    CPCOMMIT();
    for (int ib = 0; ib < 2; ++ib) {
        CPWAIT0();
        __syncthreads();
        if (ib < 1) {
            cp_tile64(AsT[1], Ab + 64, HC, t);
            cp_tile64(BsT[1], Bp + 64, HC, t);
            CPCOMMIT();
        }
        uint32_t off = (ib & 1) * bufo;
        STAGE_MMA64_LDSM(aA0 + off, aB0 + off);
        __syncthreads();
    }
#pragma unroll
    for (int mi = 0; mi < 4; ++mi) {
        int r = m0 + moff + 16 * mi + grp;
#pragma unroll
        for (int ni = 0; ni < 4; ++ni) {
            int c = n0 + noff + 8 * ni + 2 * tig;
            *(__half2*)&Cp[(size_t)r * P2 + c] = h2(acc[mi][ni][0], acc[mi][ni][1]);
            *(__half2*)&Cp[(size_t)(r + 8) * P2 + c] = h2(acc[mi][ni][2], acc[mi][ni][3]);
        }
    }
}

// ---------------- a = QK^T + 0.5*(rq + rk gathers), writes half ----------------
__global__ void __launch_bounds__(256, 2) a_tc() {
    extern __shared__ __half sh[];
    Tile AsT[2] = {(Tile)sh, (Tile)(sh + 128 * TW)};
    Tile BsT[2] = {(Tile)(sh + 2 * 128 * TW), (Tile)(sh + 3 * 128 * TW)};
    int bh = blockIdx.z, b = bh >> 5, h = bh & 31;
    const __half* A  = g_qh + (size_t)b * Ss * HC + h * Cc;
    const __half* Bt = g_kh + (size_t)b * Ss * HC + h * Cc;
    const __half* rqb = g_rqh + (size_t)bh * (Ss * P2);
    const __half* rkb = g_rkh + (size_t)bh * (Ss * P2);
    __half* Cp = g_ah + (size_t)bh * (Ss * Ss);
    int m0 = blockIdx.y * 128, n0 = blockIdx.x * 128;
    int t = threadIdx.x, lane = t & 31, wid = t >> 5;
    int grp = lane >> 2, tig = lane & 3;
    int moff = (wid >> 2) * 64, noff = (wid & 3) * 32;
    int lrow = lane & 15, lcol = (lane >> 4) * 8;
    uint32_t aA0 = smem_u32(&AsT[0][moff + lrow][lcol]);
    uint32_t aB0 = smem_u32(&BsT[0][noff + lrow][lcol]);
    const uint32_t bufo = 128 * TW * 2;
    float acc[4][4][4] = {};
    const __half* Ab = A + (size_t)m0 * HC;
    const __half* Bp = Bt + (size_t)n0 * HC;
    cp_tile64(AsT[0], Ab, HC, t);
    cp_tile64(BsT[0], Bp, HC, t);
    CPCOMMIT();
    for (int ib = 0; ib < 2; ++ib) {
        CPWAIT0();
        __syncthreads();
        if (ib < 1) {
            cp_tile64(AsT[1], Ab + 64, HC, t);
            cp_tile64(BsT[1], Bp + 64, HC, t);
            CPCOMMIT();
        }
        uint32_t off = (ib & 1) * bufo;
        STAGE_MMA64_LDSM(aA0 + off, aB0 + off);
        __syncthreads();
    }
#pragma unroll
    for (int mi = 0; mi < 4; ++mi) {
        int q0 = m0 + moff + 16 * mi + grp;
#pragma unroll
        for (int ni = 0; ni < 4; ++ni) {
            int kg = n0 + noff + 8 * ni + 2 * tig;
            float rq00 = __half2float(rqb[(size_t)q0 * P2 + kg - q0 + 512]);
            float rq01 = __half2float(rqb[(size_t)q0 * P2 + kg + 1 - q0 + 512]);
            float rq10 = __half2float(rqb[(size_t)(q0 + 8) * P2 + kg - q0 - 8 + 512]);
            float rq11 = __half2float(rqb[(size_t)(q0 + 8) * P2 + kg + 1 - q0 - 8 + 512]);
            float rk00 = __half2float(rkb[(size_t)kg * P2 + q0 - kg + 512]);
            float rk01 = __half2float(rkb[(size_t)(kg + 1) * P2 + q0 - kg - 1 + 512]);
            float rk10 = __half2float(rkb[(size_t)kg * P2 + q0 + 8 - kg + 512]);
            float rk11 = __half2float(rkb[(size_t)(kg + 1) * P2 + q0 + 7 - kg + 512]);
            *(__half2*)&Cp[(size_t)q0 * Ss + kg] =
                h2(acc[mi][ni][0] + 0.5f * (rq00 + rk00),
                   acc[mi][ni][1] + 0.5f * (rq01 + rk01));
            *(__half2*)&Cp[(size_t)(q0 + 8) * Ss + kg] =
                h2(acc[mi][ni][2] + 0.5f * (rq10 + rk10),
                   acc[mi][ni][3] + 0.5f * (rq11 + rk11));
        }
    }
}

// ---------------- final: out = a(h) @ w_pair + b_pair + yq + yk ----------------
__global__ void __launch_bounds__(256) final_tc(const float* __restrict__ bpair,
                                                float* __restrict__ out) {
    __shared__ __half At_s[128][34];
    __shared__ __half Ws[128][40];
    __shared__ float basef[128];
    int k0 = blockIdx.x * 128, q = blockIdx.y, b = blockIdx.z;
    int t = threadIdx.x, lane = t & 31, wid = t >> 5;
    int grp = lane >> 2, tig = lane & 3;
    int moff = (wid >> 2) * 64, noff = (wid & 3) * 32;
#pragma unroll
    for (int i = 0; i < 2; ++i) {
        int c = t + 256 * i;
        int r = c >> 2, c16 = (c & 3) * 8;
        cpa16(&Ws[r][c16], g_wpt + (size_t)r * 32 + c16);
    }
    CPCOMMIT();
#pragma unroll
    for (int it = 0; it < 8; ++it) {
        int id = t + 256 * it;
        int hh = id >> 6, j = id & 63;
        __half2 v = *(const __half2*)&g_ah[(((size_t)(b * 32 + hh) * Ss + q) * Ss) + k0 + 2 * j];
        At_s[2 * j][hh] = __low2half(v);
        At_s[2 * j + 1][hh] = __high2half(v);
    }
    if (t < 128) basef[t] = bpair[t] + g_yq[(size_t)(b * 512 + q) * 128 + t];
    CPWAIT0();
    __syncthreads();
    float acc[4][4][4] = {};
#pragma unroll
    for (int ks = 0; ks < 2; ++ks) {
        int koff = ks * 16 + 2 * tig;
        uint32_t af[4][4], bf[4][2];
#pragma unroll
        for (int mi = 0; mi < 4; ++mi) {
            int r = moff + 16 * mi + grp;
            af[mi][0] = *(const uint32_t*)&At_s[r][koff];
            af[mi][1] = *(const uint32_t*)&At_s[r + 8][koff];
            af[mi][2] = *(const uint32_t*)&At_s[r][koff + 8];
            af[mi][3] = *(const uint32_t*)&At_s[r + 8][koff + 8];
        }
#pragma unroll
        for (int ni = 0; ni < 4; ++ni) {
            int c = noff + 8 * ni + grp;
            bf[ni][0] = *(const uint32_t*)&Ws[c][koff];
            bf[ni][1] = *(const uint32_t*)&Ws[c][koff + 8];
        }
#pragma unroll
        for (int mi = 0; mi < 4; ++mi)
#pragma unroll
            for (int ni = 0; ni < 4; ++ni) MMA_F16(acc[mi][ni], af[mi], bf[ni]);
    }
#pragma unroll
    for (int mi = 0; mi < 4; ++mi) {
        int kl0 = moff + 16 * mi + grp;
        size_t row0 = ((size_t)(b * 512 + q) * 512 + k0 + kl0) * 128;
        size_t row1 = row0 + (size_t)8 * 128;
        const float* yk0 = &g_yk[(size_t)(b * 512 + k0 + kl0) * 128];
        const float* yk1 = yk0 + 8 * 128;
#pragma unroll
        for (int ni = 0; ni < 4; ++ni) {
            int f = noff + 8 * ni + 2 * tig;
            float2 y0 = *(const float2*)&yk0[f];
            float2 y1 = *(const float2*)&yk1[f];
            *(float2*)&out[row0 + f] = make_float2(acc[mi][ni][0] + basef[f] + y0.x,
                                                   acc[mi][ni][1] + basef[f + 1] + y0.y);
            *(float2*)&out[row1 + f] = make_float2(acc[mi][ni][2] + basef[f] + y1.x,
                                                   acc[mi][ni][3] + basef[f + 1] + y1.y);
        }
    }
}

// ---------------- launcher ----------------
extern "C" void kernel_launch(void* const* d_in, const int* in_sizes, int n_in,
                              void* d_out, int out_size) {
    const float* x        = (const float*)d_in[0];
    const float* scale    = (const float*)d_in[1];
    const float* w_q      = (const float*)d_in[2];
    const float* w_k      = (const float*)d_in[3];
    const float* w_pos    = (const float*)d_in[4];
    const float* b_pos    = (const float*)d_in[5];
    const float* q_r_bias = (const float*)d_in[6];
    const float* k_r_bias = (const float*)d_in[7];
    const float* w_yq     = (const float*)d_in[8];
    const float* w_yk     = (const float*)d_in[9];
    const float* w_pair   = (const float*)d_in[10];
    const float* b_pair   = (const float*)d_in[11];
    float* out = (float*)d_out;

    __half *p_wqt, *p_wkt, *p_wyqt, *p_wykt, *p_wpt;
    cudaGetSymbolAddress((void**)&p_wqt, g_wqt);
    cudaGetSymbolAddress((void**)&p_wkt, g_wkt);
    cudaGetSymbolAddress((void**)&p_wyqt, g_wyqt);
    cudaGetSymbolAddress((void**)&p_wykt, g_wykt);
    cudaGetSymbolAddress((void**)&p_wpt, g_wpt);

    cudaFuncSetAttribute(proj_tc, cudaFuncAttributeMaxDynamicSharedMemorySize, SMEMB);
    cudaFuncSetAttribute(ygemm_tc, cudaFuncAttributeMaxDynamicSharedMemorySize, SMEMB);
    cudaFuncSetAttribute(rel_tc, cudaFuncAttributeMaxDynamicSharedMemorySize, SMEMB);
    cudaFuncSetAttribute(a_tc, cudaFuncAttributeMaxDynamicSharedMemorySize, SMEMB);

    // launch order keeps proj_tc at slot 6 (ncu -s 5 -c 1 profiles it)
    transpose_h<<<dim3(128, 48), dim3(32, 8)>>>(w_q, p_wqt, Dd, HC);      // 1
    transpose_h<<<dim3(128, 48), dim3(32, 8)>>>(w_k, p_wkt, Dd, HC);      // 2
    pool_norm_kernel<<<1024, 384>>>(x, scale);                            // 3
    init_cw_kernel<<<1, 32>>>();                                          // 4
    fmin_kernel<<<5, 128>>>();                                            // 5
    proj_tc<<<dim3(32, 8, 2), 256, SMEMB>>>(q_r_bias, k_r_bias);          // 6 (profiled)
    suffix_kernel<<<16, 256>>>(w_pos);                                    // 7
    posenc_kernel<<<dim3(1024, 4), 256>>>(b_pos);                         // 8
    transpose_h<<<dim3(4, 48), dim3(32, 8)>>>(w_yq, p_wyqt, Dd, PAIRF);   // 9
    transpose_h<<<dim3(4, 48), dim3(32, 8)>>>(w_yk, p_wykt, Dd, PAIRF);   // 10
    transpose_h<<<dim3(4, 1), dim3(32, 8)>>>(w_pair, p_wpt, Hh, PAIRF);   // 11
    ygemm_tc<<<dim3(1, 8, 16), 256, SMEMB>>>();                           // 12
    reduce_y_kernel<<<512, 256>>>();                                      // 13
    rel_tc<<<dim3(5, 4, 128), 256, SMEMB>>>();                            // 14
    a_tc<<<dim3(4, 4, 64), 256, SMEMB>>>();                               // 15
    final_tc<<<dim3(4, 512, 2), 256>>>(b_pair, out);                      // 16
}